// round 12
// baseline (speedup 1.0000x reference)
#include <cuda_runtime.h>
#include <cuda_bf16.h>
#include <cstdint>

// ---------------- problem constants ----------------
#define B_     2
#define S_     2048
#define H_     2048
#define NH_    16
#define HD_    128
#define CACHE_ 2048
#define KV_    4096           // CACHE_ + S_
#define M_     4096           // B_*S_
#define KDIM_  2048           // H_

#define SCALE_ 0.08838834764831845f   // 1/sqrt(128)

// bf16 split scratch (allocation-free rule: __device__ globals)
static __device__ __nv_bfloat16 sXh[(size_t)M_ * KDIM_];
static __device__ __nv_bfloat16 sXl[(size_t)M_ * KDIM_];
static __device__ __nv_bfloat16 sWqh[(size_t)H_ * KDIM_];
static __device__ __nv_bfloat16 sWql[(size_t)H_ * KDIM_];
static __device__ __nv_bfloat16 sWkh[(size_t)H_ * KDIM_];
static __device__ __nv_bfloat16 sWkl[(size_t)H_ * KDIM_];
static __device__ __nv_bfloat16 sWvh[(size_t)H_ * KDIM_];
static __device__ __nv_bfloat16 sWvl[(size_t)H_ * KDIM_];
static __device__ __nv_bfloat16 sWoh[(size_t)H_ * KDIM_];
static __device__ __nv_bfloat16 sWol[(size_t)H_ * KDIM_];

// attention operand splits
static __device__ __nv_bfloat16 sQh[(size_t)B_ * NH_ * S_ * HD_];
static __device__ __nv_bfloat16 sQl[(size_t)B_ * NH_ * S_ * HD_];
static __device__ __nv_bfloat16 sKh[(size_t)B_ * NH_ * KV_ * HD_];
static __device__ __nv_bfloat16 sKl[(size_t)B_ * NH_ * KV_ * HD_];
static __device__ __nv_bfloat16 sVh[(size_t)B_ * NH_ * KV_ * HD_];
static __device__ __nv_bfloat16 sVl[(size_t)B_ * NH_ * KV_ * HD_];
// attention output splits
static __device__ __nv_bfloat16 sAh[(size_t)M_ * KDIM_];
static __device__ __nv_bfloat16 sAl[(size_t)M_ * KDIM_];

// ---------------- helpers ----------------
__device__ __forceinline__ uint32_t smem_u32(const void* p) {
    uint32_t a;
    asm("{ .reg .u64 t; cvta.to.shared.u64 t, %1; cvt.u32.u64 %0, t; }" : "=r"(a) : "l"(p));
    return a;
}

#define LDSM4(r0,r1,r2,r3,addr) \
    asm volatile("ldmatrix.sync.aligned.m8n8.x4.shared.b16 {%0,%1,%2,%3}, [%4];" \
        : "=r"(r0),"=r"(r1),"=r"(r2),"=r"(r3) : "r"(addr))

#define LDSM4T(r0,r1,r2,r3,addr) \
    asm volatile("ldmatrix.sync.aligned.m8n8.x4.trans.shared.b16 {%0,%1,%2,%3}, [%4];" \
        : "=r"(r0),"=r"(r1),"=r"(r2),"=r"(r3) : "r"(addr))

#define MMA16816(c, a, b) \
    asm volatile("mma.sync.aligned.m16n8k16.row.col.f32.bf16.bf16.f32 " \
        "{%0,%1,%2,%3}, {%4,%5,%6,%7}, {%8,%9}, {%0,%1,%2,%3};" \
        : "+f"((c)[0]),"+f"((c)[1]),"+f"((c)[2]),"+f"((c)[3]) \
        : "r"((a)[0]),"r"((a)[1]),"r"((a)[2]),"r"((a)[3]), "r"((b)[0]),"r"((b)[1]))

#define CP_ASYNC16(saddr, gaddr) \
    asm volatile("cp.async.cg.shared.global [%0], [%1], 16;" :: "r"(saddr), "l"(gaddr))
#define CP_COMMIT() asm volatile("cp.async.commit_group;" ::: "memory")
#define CP_WAIT0()  asm volatile("cp.async.wait_group 0;" ::: "memory")

__device__ __forceinline__ void store_split(__nv_bfloat16* dh, __nv_bfloat16* dl,
                                            size_t idx, float2 v) {
    __nv_bfloat16 h0 = __float2bfloat16_rn(v.x), h1 = __float2bfloat16_rn(v.y);
    __nv_bfloat16 l0 = __float2bfloat16_rn(v.x - __bfloat162float(h0));
    __nv_bfloat16 l1 = __float2bfloat16_rn(v.y - __bfloat162float(h1));
    __nv_bfloat162 hh; hh.x = h0; hh.y = h1;
    __nv_bfloat162 ll; ll.x = l0; ll.y = l1;
    *(__nv_bfloat162*)(dh + idx) = hh;
    *(__nv_bfloat162*)(dl + idx) = ll;
}

// ---------------- cache splice (+ bf16 splits) ----------------
__global__ void copy_cache_kernel(const float4* __restrict__ kc,
                                  const float4* __restrict__ vc,
                                  float4* __restrict__ ko,
                                  float4* __restrict__ vo,
                                  uint2* __restrict__ kh, uint2* __restrict__ kl,
                                  uint2* __restrict__ vh, uint2* __restrict__ vl) {
    int i = blockIdx.x * blockDim.x + threadIdx.x;
    int chunk = i >> 16;
    int rem   = i & 65535;
    size_t d = (size_t)chunk * (KV_ * HD_ / 4) + rem;
    float4 kk = kc[i];
    float4 vv = vc[i];
    ko[d] = kk;
    vo[d] = vv;
    float fk[4] = {kk.x, kk.y, kk.z, kk.w};
    float fv[4] = {vv.x, vv.y, vv.z, vv.w};
    __nv_bfloat16 khh[4], kll[4], vhh[4], vll[4];
    #pragma unroll
    for (int j = 0; j < 4; j++) {
        khh[j] = __float2bfloat16_rn(fk[j]);
        kll[j] = __float2bfloat16_rn(fk[j] - __bfloat162float(khh[j]));
        vhh[j] = __float2bfloat16_rn(fv[j]);
        vll[j] = __float2bfloat16_rn(fv[j] - __bfloat162float(vhh[j]));
    }
    kh[d] = *(uint2*)khh; kl[d] = *(uint2*)kll;
    vh[d] = *(uint2*)vhh; vl[d] = *(uint2*)vll;
}

// ---------------- fp32 -> bf16 hi/lo split ----------------
union BF4 { __nv_bfloat16 b[4]; uint2 u; };

__device__ __forceinline__ void split_one(const float4* src, uint2* hi, uint2* lo, int i) {
    float4 v = src[i];
    BF4 H, L;
    float f[4] = {v.x, v.y, v.z, v.w};
    #pragma unroll
    for (int j = 0; j < 4; j++) {
        __nv_bfloat16 h = __float2bfloat16_rn(f[j]);
        H.b[j] = h;
        L.b[j] = __float2bfloat16_rn(f[j] - __bfloat162float(h));
    }
    hi[i] = H.u;
    lo[i] = L.u;
}

__global__ void split_kernel(const float4* __restrict__ src,
                             uint2* __restrict__ hi, uint2* __restrict__ lo) {
    int i = blockIdx.x * blockDim.x + threadIdx.x;
    split_one(src, hi, lo, i);
}

__global__ void split4_kernel(const float4* s0, const float4* s1,
                              const float4* s2, const float4* s3,
                              uint2* h0, uint2* h1, uint2* h2, uint2* h3,
                              uint2* l0, uint2* l1, uint2* l2, uint2* l3) {
    int z = blockIdx.y;
    const float4* s = (z == 0) ? s0 : (z == 1) ? s1 : (z == 2) ? s2 : s3;
    uint2* h = (z == 0) ? h0 : (z == 1) ? h1 : (z == 2) ? h2 : h3;
    uint2* l = (z == 0) ? l0 : (z == 1) ? l1 : (z == 2) ? l2 : l3;
    int i = blockIdx.x * blockDim.x + threadIdx.x;
    split_one(s, h, l, i);
}

// ---------------- mma.sync bf16-split GEMM core (R8-proven: GKC=32, 16 warps) ----------------
#define GKC      32
#define GNCH     (KDIM_/GKC)           // 64
#define TPAD     40
#define TILE_B   (128*TPAD*2)          // 10240
#define BUF_B    (4*TILE_B)            // 40960 (Ah,Al,Bh,Bl)
#define GT_SMEM  (512 + 2*BUF_B)       // 82432

__device__ __forceinline__
void gemm_core(const __nv_bfloat16* __restrict__ Ah, const __nv_bfloat16* __restrict__ Al,
               const __nv_bfloat16* __restrict__ Bh, const __nv_bfloat16* __restrict__ Bl,
               const float* __restrict__ bias, float* __restrict__ dst,
               __nv_bfloat16* __restrict__ dh, __nv_bfloat16* __restrict__ dl,
               int mode, int Lrow, int off, float scale,
               char* smc, int m0, int n0)
{
    float* s_bias = (float*)smc;
    const uint32_t sbase = smem_u32(smc + 512);

    const int tid = threadIdx.x;
    const int wid = tid >> 5, lane = tid & 31;
    const int wm = (wid & 3) * 32, wn = (wid >> 2) * 32;

    if (tid < 128) s_bias[tid] = bias[n0 + tid];

    const __nv_bfloat16* srcAh = Ah + (size_t)m0 * KDIM_;
    const __nv_bfloat16* srcAl = Al + (size_t)m0 * KDIM_;
    const __nv_bfloat16* srcBh = Bh + (size_t)n0 * KDIM_;
    const __nv_bfloat16* srcBl = Bl + (size_t)n0 * KDIM_;

    const int ld_row = tid >> 2;          // 0..127
    const int ld_c16 = tid & 3;           // 16B column
    const int aRow = wm + (lane & 15);
    const uint32_t offA0 = ((uint32_t)(aRow * TPAD + ((lane >> 4) << 3))) * 2u;
    const int bRow = wn + ((lane >> 4) << 3) + (lane & 7);
    const uint32_t offB0 = ((uint32_t)(bRow * TPAD + (((lane >> 3) & 1) << 3))) * 2u;

    float acc[2][4][4];
    #pragma unroll
    for (int i = 0; i < 2; i++)
        #pragma unroll
        for (int j = 0; j < 4; j++)
            #pragma unroll
            for (int q = 0; q < 4; q++) acc[i][j][q] = 0.f;

    auto load_chunk = [&](int buf, int c0) {
        uint32_t sb = sbase + buf * BUF_B;
        uint32_t so = (uint32_t)(ld_row * TPAD + ld_c16 * 8) * 2u;
        size_t go = (size_t)ld_row * KDIM_ + c0 + ld_c16 * 8;
        CP_ASYNC16(sb + 0 * TILE_B + so, srcAh + go);
        CP_ASYNC16(sb + 1 * TILE_B + so, srcAl + go);
        CP_ASYNC16(sb + 2 * TILE_B + so, srcBh + go);
        CP_ASYNC16(sb + 3 * TILE_B + so, srcBl + go);
        CP_COMMIT();
    };

    load_chunk(0, 0);

    for (int c = 0; c < GNCH; ++c) {
        CP_WAIT0();
        __syncthreads();
        if (c + 1 < GNCH) load_chunk((c + 1) & 1, (c + 1) * GKC);

        const uint32_t bb = sbase + (c & 1) * BUF_B;
        #pragma unroll
        for (int ks = 0; ks < 2; ++ks) {
            const uint32_t ko_ = ks * 32;
            uint32_t ah[2][4], al[2][4];
            #pragma unroll
            for (int mt = 0; mt < 2; ++mt) {
                LDSM4(ah[mt][0], ah[mt][1], ah[mt][2], ah[mt][3],
                      bb + 0 * TILE_B + offA0 + mt * (16 * TPAD * 2) + ko_);
                LDSM4(al[mt][0], al[mt][1], al[mt][2], al[mt][3],
                      bb + 1 * TILE_B + offA0 + mt * (16 * TPAD * 2) + ko_);
            }
            uint32_t bh[4][2], bl[4][2];
            #pragma unroll
            for (int p = 0; p < 2; ++p) {
                uint32_t r0, r1, r2, r3;
                LDSM4(r0, r1, r2, r3,
                      bb + 2 * TILE_B + offB0 + p * (16 * TPAD * 2) + ko_);
                bh[2*p][0] = r0; bh[2*p][1] = r1; bh[2*p+1][0] = r2; bh[2*p+1][1] = r3;
                LDSM4(r0, r1, r2, r3,
                      bb + 3 * TILE_B + offB0 + p * (16 * TPAD * 2) + ko_);
                bl[2*p][0] = r0; bl[2*p][1] = r1; bl[2*p+1][0] = r2; bl[2*p+1][1] = r3;
            }
            #pragma unroll
            for (int mt = 0; mt < 2; ++mt)
                #pragma unroll
                for (int nt = 0; nt < 4; ++nt) {
                    MMA16816(acc[mt][nt], ah[mt], bh[nt]);
                    MMA16816(acc[mt][nt], ah[mt], bl[nt]);
                    MMA16816(acc[mt][nt], al[mt], bh[nt]);
                }
        }
    }
    __syncthreads();

    #pragma unroll
    for (int mt = 0; mt < 2; ++mt) {
        #pragma unroll
        for (int nt = 0; nt < 4; ++nt) {
            float* cc = acc[mt][nt];
            int row0 = m0 + wm + mt * 16 + (lane >> 2);
            int col  = wn + nt * 8 + (lane & 3) * 2;
            float2 v0 = make_float2((cc[0] + s_bias[col]) * scale,
                                    (cc[1] + s_bias[col + 1]) * scale);
            float2 v1 = make_float2((cc[2] + s_bias[col]) * scale,
                                    (cc[3] + s_bias[col + 1]) * scale);
            if (mode == 0) {
                float* p0 = dst + (size_t)row0 * H_ + n0 + col;
                *(float2*)p0 = v0;
                *(float2*)(p0 + (size_t)8 * H_) = v1;
            } else {
                int bb_ = row0 >> 11, s = row0 & (S_ - 1);
                int head = n0 >> 7;
                size_t idx = ((size_t)(bb_ * NH_ + head) * Lrow + off + s) * HD_ + (col & (HD_ - 1));
                size_t idx1 = idx + (size_t)8 * HD_;
                if (mode == 1) {
                    *(float2*)(dst + idx)  = v0;
                    *(float2*)(dst + idx1) = v1;
                }
                store_split(dh, dl, idx,  v0);
                store_split(dh, dl, idx1, v1);
            }
        }
    }
}

__global__ __launch_bounds__(512, 1)
void gemm_qkv(const __nv_bfloat16* __restrict__ xh, const __nv_bfloat16* __restrict__ xl,
              const __nv_bfloat16* __restrict__ wqh, const __nv_bfloat16* __restrict__ wql,
              const __nv_bfloat16* __restrict__ wkh, const __nv_bfloat16* __restrict__ wkl,
              const __nv_bfloat16* __restrict__ wvh, const __nv_bfloat16* __restrict__ wvl,
              const float* __restrict__ bq, const float* __restrict__ bk,
              const float* __restrict__ bv,
              float* __restrict__ ko, float* __restrict__ vo,
              __nv_bfloat16* __restrict__ qh, __nv_bfloat16* __restrict__ ql,
              __nv_bfloat16* __restrict__ kh, __nv_bfloat16* __restrict__ kl,
              __nv_bfloat16* __restrict__ vh, __nv_bfloat16* __restrict__ vl)
{
    extern __shared__ char smc[];
    const int z = blockIdx.z;
    const int n0 = blockIdx.x * 128, m0 = blockIdx.y * 128;
    if (z == 0) {
        gemm_core(xh, xl, wqh, wql, bq, nullptr, qh, ql, 2, S_, 0, SCALE_, smc, m0, n0);
    } else if (z == 1) {
        gemm_core(xh, xl, wkh, wkl, bk, ko, kh, kl, 1, KV_, CACHE_, 1.0f, smc, m0, n0);
    } else {
        gemm_core(xh, xl, wvh, wvl, bv, vo, vh, vl, 1, KV_, CACHE_, 1.0f, smc, m0, n0);
    }
}

__global__ __launch_bounds__(512, 1)
void gemm_out(const __nv_bfloat16* __restrict__ Ah, const __nv_bfloat16* __restrict__ Al,
              const __nv_bfloat16* __restrict__ Bh, const __nv_bfloat16* __restrict__ Bl,
              const float* __restrict__ bias, float* __restrict__ dst)
{
    extern __shared__ char smc[];
    gemm_core(Ah, Al, Bh, Bl, bias, dst, nullptr, nullptr, 0, 0, 0, 1.0f,
              smc, blockIdx.y * 128, blockIdx.x * 128);
}

// ---------------- flash attention via mma.sync, bf16 3-term split ----------------
// R12: 2-stage software pipeline — scores(t+1) issued BEFORE softmax(t) so the
// tensor pipe stays busy during exp/shfl/repack. 3 KV stage buffers; sacc
// double-buffered (A/B) with exp done IN PLACE (p array eliminated -> net
// register delta ~0). Ballot-skip of o-rescale retained (R10-proven).
#define AKT 32
#define QPITCH 272
#define KOFF   0
#define LOFF   8704
#define VHOFF  17408
#define VLOFF  26112
#define MSOFF  34816
#define STAGE_B 51200
#define QBYTES (128*QPITCH)              // 34816
#define QOFF   (3*STAGE_B)               // 153600
#define ATT_SMEM (3*STAGE_B + 2*QBYTES)  // 223232

__global__ __launch_bounds__(256, 1)
void attn_mma(const __nv_bfloat16* __restrict__ Qh, const __nv_bfloat16* __restrict__ Ql,
              const __nv_bfloat16* __restrict__ Kh, const __nv_bfloat16* __restrict__ Kl,
              const __nv_bfloat16* __restrict__ Vh, const __nv_bfloat16* __restrict__ Vl,
              const float* __restrict__ Msk,
              __nv_bfloat16* __restrict__ Oh, __nv_bfloat16* __restrict__ Ol)
{
    extern __shared__ char sma[];
    const uint32_t sb = smem_u32(sma);

    const int tid = threadIdx.x;
    const int wid = tid >> 5, lane = tid & 31;
    const int qt = blockIdx.x, h = blockIdx.y, b = blockIdx.z;

    const size_t bh_q = ((size_t)(b * NH_ + h) * S_ + qt * 128) * HD_;
    const size_t bh_kv = (size_t)(b * NH_ + h) * KV_ * HD_;
    const float* Mb = Msk + ((size_t)b * S_ + qt * 128) * KV_;

    const int kv_row = tid >> 3, kv_c = tid & 7;
    const int m_row = tid >> 1, m_c = (tid & 1) * 4;
    auto issue_stage = [&](int t, int buf) {
        uint32_t st = sb + buf * STAGE_B;
        size_t go = bh_kv + (size_t)(t * AKT + kv_row) * HD_ + kv_c * 8;
        uint32_t so = st + kv_row * QPITCH + kv_c * 16;
        CP_ASYNC16(so + KOFF,        Kh + go);
        CP_ASYNC16(so + KOFF + 128,  Kh + go + 64);
        CP_ASYNC16(so + LOFF,        Kl + go);
        CP_ASYNC16(so + LOFF + 128,  Kl + go + 64);
        CP_ASYNC16(so + VHOFF,       Vh + go);
        CP_ASYNC16(so + VHOFF + 128, Vh + go + 64);
        CP_ASYNC16(so + VLOFF,       Vl + go);
        CP_ASYNC16(so + VLOFF + 128, Vl + go + 64);
        const float* mp = Mb + (size_t)m_row * KV_ + t * AKT + m_c * 4;
        uint32_t md = st + MSOFF + m_row * 128 + m_c * 16;
        #pragma unroll
        for (int j = 0; j < 4; j++)
            CP_ASYNC16(md + j * 16, mp + j * 4);
    };

    // prologue: Q (into QOFF region) + stage 0, one commit group
    {
        int qr = tid >> 1, qc = (tid & 1) * 8;
        const __nv_bfloat16* qhp = Qh + bh_q + (size_t)qr * HD_ + qc * 8;
        const __nv_bfloat16* qlp = Ql + bh_q + (size_t)qr * HD_ + qc * 8;
        uint32_t d0 = sb + QOFF + qr * QPITCH + qc * 16;
        #pragma unroll
        for (int j = 0; j < 8; j++) {
            CP_ASYNC16(d0 + j * 16, qhp + j * 8);
            CP_ASYNC16(d0 + QBYTES + j * 16, qlp + j * 8);
        }
    }
    issue_stage(0, 0);
    CP_COMMIT();

    uint32_t qhF[8][4], qlF[8][4];
    float o[16][4];
    #pragma unroll
    for (int i = 0; i < 16; i++)
        #pragma unroll
        for (int j = 0; j < 4; j++) o[i][j] = 0.f;
    float m0r = -1e30f, m1r = -1e30f, l0r = 0.f, l1r = 0.f;

    const uint32_t qAoff = (uint32_t)((wid * 16 + (lane & 15)) * QPITCH + ((lane >> 4) << 3) * 2);
    const uint32_t kBrow = (uint32_t)((((lane >> 4) << 3) + (lane & 7)) * QPITCH + (((lane >> 3) & 1) << 3) * 2);
    const uint32_t vTrow = (uint32_t)(((((lane >> 3) & 1) << 3) + (lane & 7)) * QPITCH + ((lane >> 4) << 3) * 2);

    CP_WAIT0();
    __syncthreads();
    #pragma unroll
    for (int ks = 0; ks < 8; ++ks) {
        LDSM4(qhF[ks][0], qhF[ks][1], qhF[ks][2], qhF[ks][3], sb + QOFF + qAoff + ks * 32);
        LDSM4(qlF[ks][0], qlF[ks][1], qlF[ks][2], qlF[ks][3], sb + QOFF + QBYTES + qAoff + ks * 32);
    }
    issue_stage(1, 1);
    CP_COMMIT();

    float saccA[4][4], saccB[4][4];

    // scores helper: D(sc) += Q * K(stage st)
    auto do_scores = [&](uint32_t st, float (&sc)[4][4]) {
        #pragma unroll
        for (int i = 0; i < 4; i++)
            #pragma unroll
            for (int j = 0; j < 4; j++) sc[i][j] = 0.f;
        #pragma unroll
        for (int ks = 0; ks < 8; ++ks) {
            #pragma unroll
            for (int nh = 0; nh < 2; ++nh) {
                uint32_t kh0, kh1, kh2, kh3, kl0, kl1, kl2, kl3;
                uint32_t ka = st + KOFF + kBrow + nh * 16 * QPITCH + ks * 32;
                uint32_t la = st + LOFF + kBrow + nh * 16 * QPITCH + ks * 32;
                LDSM4(kh0, kh1, kh2, kh3, ka);
                LDSM4(kl0, kl1, kl2, kl3, la);
                uint32_t bh0[2] = {kh0, kh1}, bh1[2] = {kh2, kh3};
                uint32_t bl0[2] = {kl0, kl1}, bl1[2] = {kl2, kl3};
                MMA16816(sc[2*nh],   qhF[ks], bh0);
                MMA16816(sc[2*nh],   qhF[ks], bl0);
                MMA16816(sc[2*nh],   qlF[ks], bh0);
                MMA16816(sc[2*nh+1], qhF[ks], bh1);
                MMA16816(sc[2*nh+1], qhF[ks], bl1);
                MMA16816(sc[2*nh+1], qlF[ks], bh1);
            }
        }
    };

    const int NIT = KV_ / AKT;   // 128 (even)

    // scores(0) into saccA (stage buf 0)
    do_scores(sb + 0 * STAGE_B, saccA);

    // pipelined body: at entry, cur holds RAW scores of tile t; stage t+1 in flight.
    auto body = [&](int t, float (&cur)[4][4], float (&nxt)[4][4]) {
        if (t + 1 < NIT) CP_WAIT0();   // stage t+1 arrived (only group in flight)
        __syncthreads();               // all warps done with PV(t-1); stage t+1 visible
        if (t + 2 < NIT) { issue_stage(t + 2, (t + 2) % 3); CP_COMMIT(); }

        // scores for NEXT tile first — MMA pipe busy during softmax below
        if (t + 1 < NIT) do_scores(sb + ((t + 1) % 3) * STAGE_B, nxt);

        const uint32_t st = sb + (t % 3) * STAGE_B;

        // ---- softmax on cur (in place; q pre-scaled; add mask) ----
        const uint32_t msb = st + MSOFF + (wid * 16 + (lane >> 2)) * 128 + (lane & 3) * 8;
        float rm0 = -1e30f, rm1 = -1e30f;
        #pragma unroll
        for (int nt = 0; nt < 4; ++nt) {
            float2 mv0 = *(const float2*)(sma + (msb + nt * 32 - sb));
            float2 mv1 = *(const float2*)(sma + (msb + nt * 32 + 8 * 128 - sb));
            cur[nt][0] += mv0.x;
            cur[nt][1] += mv0.y;
            cur[nt][2] += mv1.x;
            cur[nt][3] += mv1.y;
            rm0 = fmaxf(rm0, fmaxf(cur[nt][0], cur[nt][1]));
            rm1 = fmaxf(rm1, fmaxf(cur[nt][2], cur[nt][3]));
        }
        rm0 = fmaxf(rm0, __shfl_xor_sync(0xffffffffu, rm0, 1));
        rm0 = fmaxf(rm0, __shfl_xor_sync(0xffffffffu, rm0, 2));
        rm1 = fmaxf(rm1, __shfl_xor_sync(0xffffffffu, rm1, 1));
        rm1 = fmaxf(rm1, __shfl_xor_sync(0xffffffffu, rm1, 2));
        float nm0 = fmaxf(m0r, rm0), nm1 = fmaxf(m1r, rm1);

        float rs0 = 0.f, rs1 = 0.f;
        #pragma unroll
        for (int nt = 0; nt < 4; ++nt) {
            cur[nt][0] = __expf(cur[nt][0] - nm0);
            cur[nt][1] = __expf(cur[nt][1] - nm0);
            cur[nt][2] = __expf(cur[nt][2] - nm1);
            cur[nt][3] = __expf(cur[nt][3] - nm1);
            rs0 += cur[nt][0] + cur[nt][1];
            rs1 += cur[nt][2] + cur[nt][3];
        }
        rs0 += __shfl_xor_sync(0xffffffffu, rs0, 1);
        rs0 += __shfl_xor_sync(0xffffffffu, rs0, 2);
        rs1 += __shfl_xor_sync(0xffffffffu, rs1, 1);
        rs1 += __shfl_xor_sync(0xffffffffu, rs1, 2);

        // ballot-skip rescale: alpha==1 exactly when max unchanged
        uint32_t need = __ballot_sync(0xffffffffu, (nm0 > m0r) || (nm1 > m1r));
        if (need) {
            float al0 = __expf(m0r - nm0), al1 = __expf(m1r - nm1);
            #pragma unroll
            for (int i = 0; i < 16; i++) {
                o[i][0] *= al0; o[i][1] *= al0;
                o[i][2] *= al1; o[i][3] *= al1;
            }
            l0r = l0r * al0 + rs0;
            l1r = l1r * al1 + rs1;
        } else {
            l0r += rs0;
            l1r += rs1;
        }
        m0r = nm0; m1r = nm1;

        // ---- P -> bf16 hi/lo A-frags ----
        uint32_t phF[2][4], plF[2][4];
        #pragma unroll
        for (int ks2 = 0; ks2 < 2; ++ks2) {
            #pragma unroll
            for (int half = 0; half < 2; ++half) {
                int nt = 2 * ks2 + half;
                #pragma unroll
                for (int rr = 0; rr < 2; ++rr) {
                    float f0 = cur[nt][2*rr], f1 = cur[nt][2*rr+1];
                    __nv_bfloat16 h0 = __float2bfloat16_rn(f0);
                    __nv_bfloat16 h1 = __float2bfloat16_rn(f1);
                    __nv_bfloat16 g0 = __float2bfloat16_rn(f0 - __bfloat162float(h0));
                    __nv_bfloat16 g1 = __float2bfloat16_rn(f1 - __bfloat162float(h1));
                    __nv_bfloat162 hp; hp.x = h0; hp.y = h1;
                    __nv_bfloat162 lp; lp.x = g0; lp.y = g1;
                    phF[ks2][half*2 + rr] = *(uint32_t*)&hp;
                    plF[ks2][half*2 + rr] = *(uint32_t*)&lp;
                }
            }
        }

        // ---- PV ----
        #pragma unroll
        for (int ks2 = 0; ks2 < 2; ++ks2) {
            #pragma unroll
            for (int vb = 0; vb < 8; ++vb) {
                uint32_t h0, h1, h2, h3, g0, g1, g2, g3;
                uint32_t va = st + VHOFF + vTrow + ks2 * 16 * QPITCH + vb * 32;
                uint32_t wa = st + VLOFF + vTrow + ks2 * 16 * QPITCH + vb * 32;
                LDSM4T(h0, h1, h2, h3, va);
                LDSM4T(g0, g1, g2, g3, wa);
                uint32_t bh0[2] = {h0, h1}, bh1[2] = {h2, h3};
                uint32_t bl0[2] = {g0, g1}, bl1[2] = {g2, g3};
                MMA16816(o[2*vb],   phF[ks2], bh0);
                MMA16816(o[2*vb],   phF[ks2], bl0);
                MMA16816(o[2*vb],   plF[ks2], bh0);
                MMA16816(o[2*vb+1], phF[ks2], bh1);
                MMA16816(o[2*vb+1], phF[ks2], bl1);
                MMA16816(o[2*vb+1], plF[ks2], bh1);
            }
        }
    };

    for (int t = 0; t < NIT; t += 2) {
        body(t,     saccA, saccB);
        body(t + 1, saccB, saccA);
    }

    float i0 = 1.0f / l0r, i1 = 1.0f / l1r;
    int r0 = qt * 128 + wid * 16 + (lane >> 2);
    size_t base0 = ((size_t)b * S_ + r0) * H_ + h * HD_ + (lane & 3) * 2;
    size_t base1 = base0 + (size_t)8 * H_;
    #pragma unroll
    for (int nt = 0; nt < 16; ++nt) {
        store_split(Oh, Ol, base0 + nt * 8, make_float2(o[nt][0] * i0, o[nt][1] * i0));
        store_split(Oh, Ol, base1 + nt * 8, make_float2(o[nt][2] * i1, o[nt][3] * i1));
    }
}

// ---------------- launch ----------------
extern "C" void kernel_launch(void* const* d_in, const int* in_sizes, int n_in,
                              void* d_out, int out_size) {
    (void)in_sizes; (void)n_in; (void)out_size;
    const float* x   = (const float*)d_in[0];
    const float* msk = (const float*)d_in[1];
    const float* kc  = (const float*)d_in[2];
    const float* vc  = (const float*)d_in[3];
    const float* Wq  = (const float*)d_in[4];
    const float* bq  = (const float*)d_in[5];
    const float* Wk  = (const float*)d_in[6];
    const float* bk  = (const float*)d_in[7];
    const float* Wv  = (const float*)d_in[8];
    const float* bv  = (const float*)d_in[9];
    const float* Wo  = (const float*)d_in[10];
    const float* bo  = (const float*)d_in[11];

    float* out = (float*)d_out;
    float* ko  = out + (size_t)B_ * S_ * H_;
    float* vo  = ko  + (size_t)B_ * NH_ * KV_ * HD_;

    __nv_bfloat16 *xh, *xl, *wqh, *wql, *wkh, *wkl, *wvh, *wvl, *woh, *wol;
    __nv_bfloat16 *qh, *ql, *kh, *kl, *vh, *vl, *ah, *al;
    cudaGetSymbolAddress((void**)&xh,  sXh);  cudaGetSymbolAddress((void**)&xl,  sXl);
    cudaGetSymbolAddress((void**)&wqh, sWqh); cudaGetSymbolAddress((void**)&wql, sWql);
    cudaGetSymbolAddress((void**)&wkh, sWkh); cudaGetSymbolAddress((void**)&wkl, sWkl);
    cudaGetSymbolAddress((void**)&wvh, sWvh); cudaGetSymbolAddress((void**)&wvl, sWvl);
    cudaGetSymbolAddress((void**)&woh, sWoh); cudaGetSymbolAddress((void**)&wol, sWol);
    cudaGetSymbolAddress((void**)&qh, sQh); cudaGetSymbolAddress((void**)&ql, sQl);
    cudaGetSymbolAddress((void**)&kh, sKh); cudaGetSymbolAddress((void**)&kl, sKl);
    cudaGetSymbolAddress((void**)&vh, sVh); cudaGetSymbolAddress((void**)&vl, sVl);
    cudaGetSymbolAddress((void**)&ah, sAh); cudaGetSymbolAddress((void**)&al, sAl);

    cudaFuncSetAttribute(gemm_qkv,
                         cudaFuncAttributeMaxDynamicSharedMemorySize, GT_SMEM);
    cudaFuncSetAttribute(gemm_out,
                         cudaFuncAttributeMaxDynamicSharedMemorySize, GT_SMEM);
    cudaFuncSetAttribute(attn_mma,
                         cudaFuncAttributeMaxDynamicSharedMemorySize, ATT_SMEM);

    // 1. splice caches into output k/v (+ splits for attention)
    copy_cache_kernel<<<8192, 256>>>((const float4*)kc, (const float4*)vc,
                                     (float4*)ko, (float4*)vo,
                                     (uint2*)kh, (uint2*)kl, (uint2*)vh, (uint2*)vl);

    // 2. bf16 hi/lo splits of inputs
    split_kernel<<<8192, 256>>>((const float4*)x, (uint2*)xh, (uint2*)xl);
    split4_kernel<<<dim3(4096, 4), 256>>>(
        (const float4*)Wq, (const float4*)Wk, (const float4*)Wv, (const float4*)Wo,
        (uint2*)wqh, (uint2*)wkh, (uint2*)wvh, (uint2*)woh,
        (uint2*)wql, (uint2*)wkl, (uint2*)wvl, (uint2*)wol);

    // 3. fused QKV projections (tensor cores); q pre-scaled by 1/sqrt(HD)
    gemm_qkv<<<dim3(H_/128, M_/128, 3), 512, GT_SMEM>>>(
        xh, xl, wqh, wql, wkh, wkl, wvh, wvl, bq, bk, bv,
        ko, vo, qh, ql, kh, kl, vh, vl);

    // 4. attention (tensor cores, 3-term bf16 split, 2-stage pipelined softmax)
    attn_mma<<<dim3(S_/128, NH_, B_), 256, ATT_SMEM>>>(qh, ql, kh, kl, vh, vl, msk, ah, al);

    // 5. output projection
    gemm_out<<<dim3(H_/128, M_/128), 512, GT_SMEM>>>(ah, al, woh, wol, bo, out);
}

// round 13
// speedup vs baseline: 1.0179x; 1.0179x over previous
#include <cuda_runtime.h>
#include <cuda_bf16.h>
#include <cstdint>

// ---------------- problem constants ----------------
#define B_     2
#define S_     2048
#define H_     2048
#define NH_    16
#define HD_    128
#define CACHE_ 2048
#define KV_    4096           // CACHE_ + S_
#define M_     4096           // B_*S_
#define KDIM_  2048           // H_

#define SCALE_ 0.08838834764831845f   // 1/sqrt(128)

// bf16 split scratch (allocation-free rule: __device__ globals)
static __device__ __nv_bfloat16 sXh[(size_t)M_ * KDIM_];
static __device__ __nv_bfloat16 sXl[(size_t)M_ * KDIM_];
static __device__ __nv_bfloat16 sWqh[(size_t)H_ * KDIM_];
static __device__ __nv_bfloat16 sWql[(size_t)H_ * KDIM_];
static __device__ __nv_bfloat16 sWkh[(size_t)H_ * KDIM_];
static __device__ __nv_bfloat16 sWkl[(size_t)H_ * KDIM_];
static __device__ __nv_bfloat16 sWvh[(size_t)H_ * KDIM_];
static __device__ __nv_bfloat16 sWvl[(size_t)H_ * KDIM_];
static __device__ __nv_bfloat16 sWoh[(size_t)H_ * KDIM_];
static __device__ __nv_bfloat16 sWol[(size_t)H_ * KDIM_];

// attention operand splits
static __device__ __nv_bfloat16 sQh[(size_t)B_ * NH_ * S_ * HD_];
static __device__ __nv_bfloat16 sQl[(size_t)B_ * NH_ * S_ * HD_];
static __device__ __nv_bfloat16 sKh[(size_t)B_ * NH_ * KV_ * HD_];
static __device__ __nv_bfloat16 sKl[(size_t)B_ * NH_ * KV_ * HD_];
static __device__ __nv_bfloat16 sVh[(size_t)B_ * NH_ * KV_ * HD_];
static __device__ __nv_bfloat16 sVl[(size_t)B_ * NH_ * KV_ * HD_];
// attention output splits
static __device__ __nv_bfloat16 sAh[(size_t)M_ * KDIM_];
static __device__ __nv_bfloat16 sAl[(size_t)M_ * KDIM_];

// ---------------- helpers ----------------
__device__ __forceinline__ uint32_t smem_u32(const void* p) {
    uint32_t a;
    asm("{ .reg .u64 t; cvta.to.shared.u64 t, %1; cvt.u32.u64 %0, t; }" : "=r"(a) : "l"(p));
    return a;
}

#define LDSM4(r0,r1,r2,r3,addr) \
    asm volatile("ldmatrix.sync.aligned.m8n8.x4.shared.b16 {%0,%1,%2,%3}, [%4];" \
        : "=r"(r0),"=r"(r1),"=r"(r2),"=r"(r3) : "r"(addr))

#define LDSM4T(r0,r1,r2,r3,addr) \
    asm volatile("ldmatrix.sync.aligned.m8n8.x4.trans.shared.b16 {%0,%1,%2,%3}, [%4];" \
        : "=r"(r0),"=r"(r1),"=r"(r2),"=r"(r3) : "r"(addr))

#define MMA16816(c, a, b) \
    asm volatile("mma.sync.aligned.m16n8k16.row.col.f32.bf16.bf16.f32 " \
        "{%0,%1,%2,%3}, {%4,%5,%6,%7}, {%8,%9}, {%0,%1,%2,%3};" \
        : "+f"((c)[0]),"+f"((c)[1]),"+f"((c)[2]),"+f"((c)[3]) \
        : "r"((a)[0]),"r"((a)[1]),"r"((a)[2]),"r"((a)[3]), "r"((b)[0]),"r"((b)[1]))

#define CP_ASYNC16(saddr, gaddr) \
    asm volatile("cp.async.cg.shared.global [%0], [%1], 16;" :: "r"(saddr), "l"(gaddr))
#define CP_COMMIT() asm volatile("cp.async.commit_group;" ::: "memory")
#define CP_WAIT0()  asm volatile("cp.async.wait_group 0;" ::: "memory")

__device__ __forceinline__ void store_split(__nv_bfloat16* dh, __nv_bfloat16* dl,
                                            size_t idx, float2 v) {
    __nv_bfloat16 h0 = __float2bfloat16_rn(v.x), h1 = __float2bfloat16_rn(v.y);
    __nv_bfloat16 l0 = __float2bfloat16_rn(v.x - __bfloat162float(h0));
    __nv_bfloat16 l1 = __float2bfloat16_rn(v.y - __bfloat162float(h1));
    __nv_bfloat162 hh; hh.x = h0; hh.y = h1;
    __nv_bfloat162 ll; ll.x = l0; ll.y = l1;
    *(__nv_bfloat162*)(dh + idx) = hh;
    *(__nv_bfloat162*)(dl + idx) = ll;
}

// ---------------- cache splice (+ bf16 splits) ----------------
__global__ void copy_cache_kernel(const float4* __restrict__ kc,
                                  const float4* __restrict__ vc,
                                  float4* __restrict__ ko,
                                  float4* __restrict__ vo,
                                  uint2* __restrict__ kh, uint2* __restrict__ kl,
                                  uint2* __restrict__ vh, uint2* __restrict__ vl) {
    int i = blockIdx.x * blockDim.x + threadIdx.x;
    int chunk = i >> 16;
    int rem   = i & 65535;
    size_t d = (size_t)chunk * (KV_ * HD_ / 4) + rem;
    float4 kk = kc[i];
    float4 vv = vc[i];
    ko[d] = kk;
    vo[d] = vv;
    float fk[4] = {kk.x, kk.y, kk.z, kk.w};
    float fv[4] = {vv.x, vv.y, vv.z, vv.w};
    __nv_bfloat16 khh[4], kll[4], vhh[4], vll[4];
    #pragma unroll
    for (int j = 0; j < 4; j++) {
        khh[j] = __float2bfloat16_rn(fk[j]);
        kll[j] = __float2bfloat16_rn(fk[j] - __bfloat162float(khh[j]));
        vhh[j] = __float2bfloat16_rn(fv[j]);
        vll[j] = __float2bfloat16_rn(fv[j] - __bfloat162float(vhh[j]));
    }
    kh[d] = *(uint2*)khh; kl[d] = *(uint2*)kll;
    vh[d] = *(uint2*)vhh; vl[d] = *(uint2*)vll;
}

// ---------------- fp32 -> bf16 hi/lo split ----------------
union BF4 { __nv_bfloat16 b[4]; uint2 u; };

__device__ __forceinline__ void split_one(const float4* src, uint2* hi, uint2* lo, int i) {
    float4 v = src[i];
    BF4 H, L;
    float f[4] = {v.x, v.y, v.z, v.w};
    #pragma unroll
    for (int j = 0; j < 4; j++) {
        __nv_bfloat16 h = __float2bfloat16_rn(f[j]);
        H.b[j] = h;
        L.b[j] = __float2bfloat16_rn(f[j] - __bfloat162float(h));
    }
    hi[i] = H.u;
    lo[i] = L.u;
}

__global__ void split_kernel(const float4* __restrict__ src,
                             uint2* __restrict__ hi, uint2* __restrict__ lo) {
    int i = blockIdx.x * blockDim.x + threadIdx.x;
    split_one(src, hi, lo, i);
}

__global__ void split4_kernel(const float4* s0, const float4* s1,
                              const float4* s2, const float4* s3,
                              uint2* h0, uint2* h1, uint2* h2, uint2* h3,
                              uint2* l0, uint2* l1, uint2* l2, uint2* l3) {
    int z = blockIdx.y;
    const float4* s = (z == 0) ? s0 : (z == 1) ? s1 : (z == 2) ? s2 : s3;
    uint2* h = (z == 0) ? h0 : (z == 1) ? h1 : (z == 2) ? h2 : h3;
    uint2* l = (z == 0) ? l0 : (z == 1) ? l1 : (z == 2) ? l2 : l3;
    int i = blockIdx.x * blockDim.x + threadIdx.x;
    split_one(s, h, l, i);
}

// ---------------- mma.sync bf16-split GEMM core (R8-proven: GKC=32, 16 warps) ----------------
#define GKC      32
#define GNCH     (KDIM_/GKC)           // 64
#define TPAD     40
#define TILE_B   (128*TPAD*2)          // 10240
#define BUF_B    (4*TILE_B)            // 40960 (Ah,Al,Bh,Bl)
#define GT_SMEM  (512 + 2*BUF_B)       // 82432

__device__ __forceinline__
void gemm_core(const __nv_bfloat16* __restrict__ Ah, const __nv_bfloat16* __restrict__ Al,
               const __nv_bfloat16* __restrict__ Bh, const __nv_bfloat16* __restrict__ Bl,
               const float* __restrict__ bias, float* __restrict__ dst,
               __nv_bfloat16* __restrict__ dh, __nv_bfloat16* __restrict__ dl,
               int mode, int Lrow, int off, float scale,
               char* smc, int m0, int n0)
{
    float* s_bias = (float*)smc;
    const uint32_t sbase = smem_u32(smc + 512);

    const int tid = threadIdx.x;
    const int wid = tid >> 5, lane = tid & 31;
    const int wm = (wid & 3) * 32, wn = (wid >> 2) * 32;

    if (tid < 128) s_bias[tid] = bias[n0 + tid];

    const __nv_bfloat16* srcAh = Ah + (size_t)m0 * KDIM_;
    const __nv_bfloat16* srcAl = Al + (size_t)m0 * KDIM_;
    const __nv_bfloat16* srcBh = Bh + (size_t)n0 * KDIM_;
    const __nv_bfloat16* srcBl = Bl + (size_t)n0 * KDIM_;

    const int ld_row = tid >> 2;          // 0..127
    const int ld_c16 = tid & 3;           // 16B column
    const int aRow = wm + (lane & 15);
    const uint32_t offA0 = ((uint32_t)(aRow * TPAD + ((lane >> 4) << 3))) * 2u;
    const int bRow = wn + ((lane >> 4) << 3) + (lane & 7);
    const uint32_t offB0 = ((uint32_t)(bRow * TPAD + (((lane >> 3) & 1) << 3))) * 2u;

    float acc[2][4][4];
    #pragma unroll
    for (int i = 0; i < 2; i++)
        #pragma unroll
        for (int j = 0; j < 4; j++)
            #pragma unroll
            for (int q = 0; q < 4; q++) acc[i][j][q] = 0.f;

    auto load_chunk = [&](int buf, int c0) {
        uint32_t sb = sbase + buf * BUF_B;
        uint32_t so = (uint32_t)(ld_row * TPAD + ld_c16 * 8) * 2u;
        size_t go = (size_t)ld_row * KDIM_ + c0 + ld_c16 * 8;
        CP_ASYNC16(sb + 0 * TILE_B + so, srcAh + go);
        CP_ASYNC16(sb + 1 * TILE_B + so, srcAl + go);
        CP_ASYNC16(sb + 2 * TILE_B + so, srcBh + go);
        CP_ASYNC16(sb + 3 * TILE_B + so, srcBl + go);
        CP_COMMIT();
    };

    load_chunk(0, 0);

    for (int c = 0; c < GNCH; ++c) {
        CP_WAIT0();
        __syncthreads();
        if (c + 1 < GNCH) load_chunk((c + 1) & 1, (c + 1) * GKC);

        const uint32_t bb = sbase + (c & 1) * BUF_B;
        #pragma unroll
        for (int ks = 0; ks < 2; ++ks) {
            const uint32_t ko_ = ks * 32;
            uint32_t ah[2][4], al[2][4];
            #pragma unroll
            for (int mt = 0; mt < 2; ++mt) {
                LDSM4(ah[mt][0], ah[mt][1], ah[mt][2], ah[mt][3],
                      bb + 0 * TILE_B + offA0 + mt * (16 * TPAD * 2) + ko_);
                LDSM4(al[mt][0], al[mt][1], al[mt][2], al[mt][3],
                      bb + 1 * TILE_B + offA0 + mt * (16 * TPAD * 2) + ko_);
            }
            uint32_t bh[4][2], bl[4][2];
            #pragma unroll
            for (int p = 0; p < 2; ++p) {
                uint32_t r0, r1, r2, r3;
                LDSM4(r0, r1, r2, r3,
                      bb + 2 * TILE_B + offB0 + p * (16 * TPAD * 2) + ko_);
                bh[2*p][0] = r0; bh[2*p][1] = r1; bh[2*p+1][0] = r2; bh[2*p+1][1] = r3;
                LDSM4(r0, r1, r2, r3,
                      bb + 3 * TILE_B + offB0 + p * (16 * TPAD * 2) + ko_);
                bl[2*p][0] = r0; bl[2*p][1] = r1; bl[2*p+1][0] = r2; bl[2*p+1][1] = r3;
            }
            #pragma unroll
            for (int mt = 0; mt < 2; ++mt)
                #pragma unroll
                for (int nt = 0; nt < 4; ++nt) {
                    MMA16816(acc[mt][nt], ah[mt], bh[nt]);
                    MMA16816(acc[mt][nt], ah[mt], bl[nt]);
                    MMA16816(acc[mt][nt], al[mt], bh[nt]);
                }
        }
    }
    __syncthreads();

    #pragma unroll
    for (int mt = 0; mt < 2; ++mt) {
        #pragma unroll
        for (int nt = 0; nt < 4; ++nt) {
            float* cc = acc[mt][nt];
            int row0 = m0 + wm + mt * 16 + (lane >> 2);
            int col  = wn + nt * 8 + (lane & 3) * 2;
            float2 v0 = make_float2((cc[0] + s_bias[col]) * scale,
                                    (cc[1] + s_bias[col + 1]) * scale);
            float2 v1 = make_float2((cc[2] + s_bias[col]) * scale,
                                    (cc[3] + s_bias[col + 1]) * scale);
            if (mode == 0) {
                float* p0 = dst + (size_t)row0 * H_ + n0 + col;
                *(float2*)p0 = v0;
                *(float2*)(p0 + (size_t)8 * H_) = v1;
            } else {
                int bb_ = row0 >> 11, s = row0 & (S_ - 1);
                int head = n0 >> 7;
                size_t idx = ((size_t)(bb_ * NH_ + head) * Lrow + off + s) * HD_ + (col & (HD_ - 1));
                size_t idx1 = idx + (size_t)8 * HD_;
                if (mode == 1) {
                    *(float2*)(dst + idx)  = v0;
                    *(float2*)(dst + idx1) = v1;
                }
                store_split(dh, dl, idx,  v0);
                store_split(dh, dl, idx1, v1);
            }
        }
    }
}

__global__ __launch_bounds__(512, 1)
void gemm_qkv(const __nv_bfloat16* __restrict__ xh, const __nv_bfloat16* __restrict__ xl,
              const __nv_bfloat16* __restrict__ wqh, const __nv_bfloat16* __restrict__ wql,
              const __nv_bfloat16* __restrict__ wkh, const __nv_bfloat16* __restrict__ wkl,
              const __nv_bfloat16* __restrict__ wvh, const __nv_bfloat16* __restrict__ wvl,
              const float* __restrict__ bq, const float* __restrict__ bk,
              const float* __restrict__ bv,
              float* __restrict__ ko, float* __restrict__ vo,
              __nv_bfloat16* __restrict__ qh, __nv_bfloat16* __restrict__ ql,
              __nv_bfloat16* __restrict__ kh, __nv_bfloat16* __restrict__ kl,
              __nv_bfloat16* __restrict__ vh, __nv_bfloat16* __restrict__ vl)
{
    extern __shared__ char smc[];
    const int z = blockIdx.z;
    const int n0 = blockIdx.x * 128, m0 = blockIdx.y * 128;
    if (z == 0) {
        gemm_core(xh, xl, wqh, wql, bq, nullptr, qh, ql, 2, S_, 0, SCALE_, smc, m0, n0);
    } else if (z == 1) {
        gemm_core(xh, xl, wkh, wkl, bk, ko, kh, kl, 1, KV_, CACHE_, 1.0f, smc, m0, n0);
    } else {
        gemm_core(xh, xl, wvh, wvl, bv, vo, vh, vl, 1, KV_, CACHE_, 1.0f, smc, m0, n0);
    }
}

__global__ __launch_bounds__(512, 1)
void gemm_out(const __nv_bfloat16* __restrict__ Ah, const __nv_bfloat16* __restrict__ Al,
              const __nv_bfloat16* __restrict__ Bh, const __nv_bfloat16* __restrict__ Bl,
              const float* __restrict__ bias, float* __restrict__ dst)
{
    extern __shared__ char smc[];
    gemm_core(Ah, Al, Bh, Bl, bias, dst, nullptr, nullptr, 0, 0, 0, 1.0f,
              smc, blockIdx.y * 128, blockIdx.x * 128);
}

// ---------------- flash attention via mma.sync, bf16 3-term split ----------------
// R13: 64-row q tiles, 128 threads (4 warps, warp = m16 x full n), mask via
// direct LDG (L2-resident; shared across heads) instead of smem staging.
// ATT_SMEM = 104448 -> 2 CTAs/SM: independent CTAs fill each other's softmax
// bubbles via the hardware scheduler (intra-CTA reordering failed in R9/R12).
// Per-warp inner loop byte-identical to R11 (proven). Ballot-skip retained.
#define AKT 32
#define QPITCH 272
#define KOFF   0
#define LOFF   8704
#define VHOFF  17408
#define VLOFF  26112
#define STAGE_B 34816                    // 4 tiles x 32 rows x 272B
#define QROWS  64
#define QBYTES (QROWS*QPITCH)            // 17408
#define QOFF   (2*STAGE_B)               // 69632
#define ATT_SMEM (2*STAGE_B + 2*QBYTES)  // 104448

__global__ __launch_bounds__(128, 2)
void attn_mma(const __nv_bfloat16* __restrict__ Qh, const __nv_bfloat16* __restrict__ Ql,
              const __nv_bfloat16* __restrict__ Kh, const __nv_bfloat16* __restrict__ Kl,
              const __nv_bfloat16* __restrict__ Vh, const __nv_bfloat16* __restrict__ Vl,
              const float* __restrict__ Msk,
              __nv_bfloat16* __restrict__ Oh, __nv_bfloat16* __restrict__ Ol)
{
    extern __shared__ char sma[];
    const uint32_t sb = smem_u32(sma);

    const int tid = threadIdx.x;
    const int wid = tid >> 5, lane = tid & 31;   // wid 0..3
    const int qt = blockIdx.x, h = blockIdx.y, b = blockIdx.z;

    const size_t bh_q = ((size_t)(b * NH_ + h) * S_ + qt * QROWS) * HD_;
    const size_t bh_kv = (size_t)(b * NH_ + h) * KV_ * HD_;
    const float* Mb = Msk + ((size_t)b * S_ + qt * QROWS) * KV_;

    // --- Q cp.async (both splits): 64 rows x 256B, 2 threads/row ---
    {
        int qr = tid >> 1, qhalf = (tid & 1) * 128;   // byte offset within row
        const __nv_bfloat16* qhp = Qh + bh_q + (size_t)qr * HD_ + (tid & 1) * 64;
        const __nv_bfloat16* qlp = Ql + bh_q + (size_t)qr * HD_ + (tid & 1) * 64;
        uint32_t d0 = sb + QOFF + qr * QPITCH + qhalf;
        #pragma unroll
        for (int j = 0; j < 8; j++) {
            CP_ASYNC16(d0 + j * 16, qhp + j * 8);
            CP_ASYNC16(d0 + QBYTES + j * 16, qlp + j * 8);
        }
    }
    // --- KV stage loader: 4 tiles x 32 rows x 256B; 128 thr -> 4 x16B per tile ---
    const int kv_row = tid >> 2;          // 0..31
    const int kv_c   = tid & 3;           // 16B chunk base
    auto issue_stage = [&](int t) {
        uint32_t st = sb + (t & 1) * STAGE_B;
        size_t g0 = bh_kv + (size_t)(t * AKT + kv_row) * HD_ + kv_c * 8;
        uint32_t s0 = st + kv_row * QPITCH + kv_c * 16;
        #pragma unroll
        for (int j = 0; j < 4; j++) {
            CP_ASYNC16(s0 + KOFF  + j * 64, Kh + g0 + j * 32);
            CP_ASYNC16(s0 + LOFF  + j * 64, Kl + g0 + j * 32);
            CP_ASYNC16(s0 + VHOFF + j * 64, Vh + g0 + j * 32);
            CP_ASYNC16(s0 + VLOFF + j * 64, Vl + g0 + j * 32);
        }
    };
    issue_stage(0);
    CP_COMMIT();

    uint32_t qhF[8][4], qlF[8][4];
    float o[16][4];
    #pragma unroll
    for (int i = 0; i < 16; i++)
        #pragma unroll
        for (int j = 0; j < 4; j++) o[i][j] = 0.f;
    float m0r = -1e30f, m1r = -1e30f, l0r = 0.f, l1r = 0.f;

    const uint32_t qAoff = (uint32_t)((wid * 16 + (lane & 15)) * QPITCH + ((lane >> 4) << 3) * 2);
    const uint32_t kBrow = (uint32_t)((((lane >> 4) << 3) + (lane & 7)) * QPITCH + (((lane >> 3) & 1) << 3) * 2);
    const uint32_t vTrow = (uint32_t)(((((lane >> 3) & 1) << 3) + (lane & 7)) * QPITCH + ((lane >> 4) << 3) * 2);

    // mask row pointers for this thread (fragment rows r and r+8)
    const float* Mrow0 = Mb + (size_t)(wid * 16 + (lane >> 2)) * KV_ + (lane & 3) * 2;
    const float* Mrow1 = Mrow0 + (size_t)8 * KV_;

    const int NIT = KV_ / AKT;   // 128
    for (int t = 0; t < NIT; ++t) {
        CP_WAIT0();
        __syncthreads();
        if (t + 1 < NIT) { issue_stage(t + 1); CP_COMMIT(); }

        if (t == 0) {
            #pragma unroll
            for (int ks = 0; ks < 8; ++ks) {
                LDSM4(qhF[ks][0], qhF[ks][1], qhF[ks][2], qhF[ks][3], sb + QOFF + qAoff + ks * 32);
                LDSM4(qlF[ks][0], qlF[ks][1], qlF[ks][2], qlF[ks][3], sb + QOFF + QBYTES + qAoff + ks * 32);
            }
        }

        const uint32_t st = sb + (t & 1) * STAGE_B;

        // ---- issue mask LDGs early (L2-resident; hidden under scores MMAs) ----
        float2 mk0[4], mk1[4];
        #pragma unroll
        for (int nt = 0; nt < 4; ++nt) {
            mk0[nt] = *(const float2*)(Mrow0 + t * AKT + nt * 8);
            mk1[nt] = *(const float2*)(Mrow1 + t * AKT + nt * 8);
        }

        // ---- scores ----
        float sacc[4][4];
        #pragma unroll
        for (int i = 0; i < 4; i++)
            #pragma unroll
            for (int j = 0; j < 4; j++) sacc[i][j] = 0.f;

        #pragma unroll
        for (int ks = 0; ks < 8; ++ks) {
            #pragma unroll
            for (int nh = 0; nh < 2; ++nh) {
                uint32_t kh0, kh1, kh2, kh3, kl0, kl1, kl2, kl3;
                uint32_t ka = st + KOFF + kBrow + nh * 16 * QPITCH + ks * 32;
                uint32_t la = st + LOFF + kBrow + nh * 16 * QPITCH + ks * 32;
                LDSM4(kh0, kh1, kh2, kh3, ka);
                LDSM4(kl0, kl1, kl2, kl3, la);
                uint32_t bh0[2] = {kh0, kh1}, bh1[2] = {kh2, kh3};
                uint32_t bl0[2] = {kl0, kl1}, bl1[2] = {kl2, kl3};
                MMA16816(sacc[2*nh],   qhF[ks], bh0);
                MMA16816(sacc[2*nh],   qhF[ks], bl0);
                MMA16816(sacc[2*nh],   qlF[ks], bh0);
                MMA16816(sacc[2*nh+1], qhF[ks], bh1);
                MMA16816(sacc[2*nh+1], qhF[ks], bl1);
                MMA16816(sacc[2*nh+1], qlF[ks], bh1);
            }
        }

        // ---- softmax (q pre-scaled; add mask from registers) ----
        float p[4][4];
        float rm0 = -1e30f, rm1 = -1e30f;
        #pragma unroll
        for (int nt = 0; nt < 4; ++nt) {
            p[nt][0] = sacc[nt][0] + mk0[nt].x;
            p[nt][1] = sacc[nt][1] + mk0[nt].y;
            p[nt][2] = sacc[nt][2] + mk1[nt].x;
            p[nt][3] = sacc[nt][3] + mk1[nt].y;
            rm0 = fmaxf(rm0, fmaxf(p[nt][0], p[nt][1]));
            rm1 = fmaxf(rm1, fmaxf(p[nt][2], p[nt][3]));
        }
        rm0 = fmaxf(rm0, __shfl_xor_sync(0xffffffffu, rm0, 1));
        rm0 = fmaxf(rm0, __shfl_xor_sync(0xffffffffu, rm0, 2));
        rm1 = fmaxf(rm1, __shfl_xor_sync(0xffffffffu, rm1, 1));
        rm1 = fmaxf(rm1, __shfl_xor_sync(0xffffffffu, rm1, 2));
        float nm0 = fmaxf(m0r, rm0), nm1 = fmaxf(m1r, rm1);

        float rs0 = 0.f, rs1 = 0.f;
        #pragma unroll
        for (int nt = 0; nt < 4; ++nt) {
            p[nt][0] = __expf(p[nt][0] - nm0);
            p[nt][1] = __expf(p[nt][1] - nm0);
            p[nt][2] = __expf(p[nt][2] - nm1);
            p[nt][3] = __expf(p[nt][3] - nm1);
            rs0 += p[nt][0] + p[nt][1];
            rs1 += p[nt][2] + p[nt][3];
        }
        rs0 += __shfl_xor_sync(0xffffffffu, rs0, 1);
        rs0 += __shfl_xor_sync(0xffffffffu, rs0, 2);
        rs1 += __shfl_xor_sync(0xffffffffu, rs1, 1);
        rs1 += __shfl_xor_sync(0xffffffffu, rs1, 2);

        // ballot-skip rescale: alpha==1 exactly when max unchanged
        uint32_t need = __ballot_sync(0xffffffffu, (nm0 > m0r) || (nm1 > m1r));
        if (need) {
            float al0 = __expf(m0r - nm0), al1 = __expf(m1r - nm1);
            #pragma unroll
            for (int i = 0; i < 16; i++) {
                o[i][0] *= al0; o[i][1] *= al0;
                o[i][2] *= al1; o[i][3] *= al1;
            }
            l0r = l0r * al0 + rs0;
            l1r = l1r * al1 + rs1;
        } else {
            l0r += rs0;
            l1r += rs1;
        }
        m0r = nm0; m1r = nm1;

        // ---- P -> bf16 hi/lo A-frags ----
        uint32_t phF[2][4], plF[2][4];
        #pragma unroll
        for (int ks2 = 0; ks2 < 2; ++ks2) {
            #pragma unroll
            for (int half = 0; half < 2; ++half) {
                int nt = 2 * ks2 + half;
                #pragma unroll
                for (int rr = 0; rr < 2; ++rr) {
                    float f0 = p[nt][2*rr], f1 = p[nt][2*rr+1];
                    __nv_bfloat16 h0 = __float2bfloat16_rn(f0);
                    __nv_bfloat16 h1 = __float2bfloat16_rn(f1);
                    __nv_bfloat16 g0 = __float2bfloat16_rn(f0 - __bfloat162float(h0));
                    __nv_bfloat16 g1 = __float2bfloat16_rn(f1 - __bfloat162float(h1));
                    __nv_bfloat162 hp; hp.x = h0; hp.y = h1;
                    __nv_bfloat162 lp; lp.x = g0; lp.y = g1;
                    phF[ks2][half*2 + rr] = *(uint32_t*)&hp;
                    plF[ks2][half*2 + rr] = *(uint32_t*)&lp;
                }
            }
        }

        // ---- PV ----
        #pragma unroll
        for (int ks2 = 0; ks2 < 2; ++ks2) {
            #pragma unroll
            for (int vb = 0; vb < 8; ++vb) {
                uint32_t h0, h1, h2, h3, g0, g1, g2, g3;
                uint32_t va = st + VHOFF + vTrow + ks2 * 16 * QPITCH + vb * 32;
                uint32_t wa = st + VLOFF + vTrow + ks2 * 16 * QPITCH + vb * 32;
                LDSM4T(h0, h1, h2, h3, va);
                LDSM4T(g0, g1, g2, g3, wa);
                uint32_t bh0[2] = {h0, h1}, bh1[2] = {h2, h3};
                uint32_t bl0[2] = {g0, g1}, bl1[2] = {g2, g3};
                MMA16816(o[2*vb],   phF[ks2], bh0);
                MMA16816(o[2*vb],   phF[ks2], bl0);
                MMA16816(o[2*vb],   plF[ks2], bh0);
                MMA16816(o[2*vb+1], phF[ks2], bh1);
                MMA16816(o[2*vb+1], phF[ks2], bl1);
                MMA16816(o[2*vb+1], plF[ks2], bh1);
            }
        }
    }

    float i0 = 1.0f / l0r, i1 = 1.0f / l1r;
    int r0 = qt * QROWS + wid * 16 + (lane >> 2);
    size_t base0 = ((size_t)b * S_ + r0) * H_ + h * HD_ + (lane & 3) * 2;
    size_t base1 = base0 + (size_t)8 * H_;
    #pragma unroll
    for (int nt = 0; nt < 16; ++nt) {
        store_split(Oh, Ol, base0 + nt * 8, make_float2(o[nt][0] * i0, o[nt][1] * i0));
        store_split(Oh, Ol, base1 + nt * 8, make_float2(o[nt][2] * i1, o[nt][3] * i1));
    }
}

// ---------------- launch ----------------
extern "C" void kernel_launch(void* const* d_in, const int* in_sizes, int n_in,
                              void* d_out, int out_size) {
    (void)in_sizes; (void)n_in; (void)out_size;
    const float* x   = (const float*)d_in[0];
    const float* msk = (const float*)d_in[1];
    const float* kc  = (const float*)d_in[2];
    const float* vc  = (const float*)d_in[3];
    const float* Wq  = (const float*)d_in[4];
    const float* bq  = (const float*)d_in[5];
    const float* Wk  = (const float*)d_in[6];
    const float* bk  = (const float*)d_in[7];
    const float* Wv  = (const float*)d_in[8];
    const float* bv  = (const float*)d_in[9];
    const float* Wo  = (const float*)d_in[10];
    const float* bo  = (const float*)d_in[11];

    float* out = (float*)d_out;
    float* ko  = out + (size_t)B_ * S_ * H_;
    float* vo  = ko  + (size_t)B_ * NH_ * KV_ * HD_;

    __nv_bfloat16 *xh, *xl, *wqh, *wql, *wkh, *wkl, *wvh, *wvl, *woh, *wol;
    __nv_bfloat16 *qh, *ql, *kh, *kl, *vh, *vl, *ah, *al;
    cudaGetSymbolAddress((void**)&xh,  sXh);  cudaGetSymbolAddress((void**)&xl,  sXl);
    cudaGetSymbolAddress((void**)&wqh, sWqh); cudaGetSymbolAddress((void**)&wql, sWql);
    cudaGetSymbolAddress((void**)&wkh, sWkh); cudaGetSymbolAddress((void**)&wkl, sWkl);
    cudaGetSymbolAddress((void**)&wvh, sWvh); cudaGetSymbolAddress((void**)&wvl, sWvl);
    cudaGetSymbolAddress((void**)&woh, sWoh); cudaGetSymbolAddress((void**)&wol, sWol);
    cudaGetSymbolAddress((void**)&qh, sQh); cudaGetSymbolAddress((void**)&ql, sQl);
    cudaGetSymbolAddress((void**)&kh, sKh); cudaGetSymbolAddress((void**)&kl, sKl);
    cudaGetSymbolAddress((void**)&vh, sVh); cudaGetSymbolAddress((void**)&vl, sVl);
    cudaGetSymbolAddress((void**)&ah, sAh); cudaGetSymbolAddress((void**)&al, sAl);

    cudaFuncSetAttribute(gemm_qkv,
                         cudaFuncAttributeMaxDynamicSharedMemorySize, GT_SMEM);
    cudaFuncSetAttribute(gemm_out,
                         cudaFuncAttributeMaxDynamicSharedMemorySize, GT_SMEM);
    cudaFuncSetAttribute(attn_mma,
                         cudaFuncAttributeMaxDynamicSharedMemorySize, ATT_SMEM);

    // 1. splice caches into output k/v (+ splits for attention)
    copy_cache_kernel<<<8192, 256>>>((const float4*)kc, (const float4*)vc,
                                     (float4*)ko, (float4*)vo,
                                     (uint2*)kh, (uint2*)kl, (uint2*)vh, (uint2*)vl);

    // 2. bf16 hi/lo splits of inputs
    split_kernel<<<8192, 256>>>((const float4*)x, (uint2*)xh, (uint2*)xl);
    split4_kernel<<<dim3(4096, 4), 256>>>(
        (const float4*)Wq, (const float4*)Wk, (const float4*)Wv, (const float4*)Wo,
        (uint2*)wqh, (uint2*)wkh, (uint2*)wvh, (uint2*)woh,
        (uint2*)wql, (uint2*)wkl, (uint2*)wvl, (uint2*)wol);

    // 3. fused QKV projections (tensor cores); q pre-scaled by 1/sqrt(HD)
    gemm_qkv<<<dim3(H_/128, M_/128, 3), 512, GT_SMEM>>>(
        xh, xl, wqh, wql, wkh, wkl, wvh, wvl, bq, bk, bv,
        ko, vo, qh, ql, kh, kl, vh, vl);

    // 4. attention: 64-row q tiles, 2 CTAs/SM, mask via LDG
    attn_mma<<<dim3(S_/QROWS, NH_, B_), 128, ATT_SMEM>>>(qh, ql, kh, kl, vh, vl, msk, ah, al);

    // 5. output projection
    gemm_out<<<dim3(H_/128, M_/128), 512, GT_SMEM>>>(ah, al, woh, wol, bo, out);
}

// round 14
// speedup vs baseline: 1.2833x; 1.2608x over previous
#include <cuda_runtime.h>
#include <cuda_bf16.h>
#include <cuda_fp16.h>
#include <cstdint>

// ---------------- problem constants ----------------
#define B_     2
#define S_     2048
#define H_     2048
#define NH_    16
#define HD_    128
#define CACHE_ 2048
#define KV_    4096           // CACHE_ + S_
#define M_     4096           // B_*S_
#define KDIM_  2048           // H_

#define SCALE_ 0.08838834764831845f   // 1/sqrt(128)

// bf16 split scratch (GEMMs keep 3-term bf16: k/v/out accuracy 3e-5)
static __device__ __nv_bfloat16 sXh[(size_t)M_ * KDIM_];
static __device__ __nv_bfloat16 sXl[(size_t)M_ * KDIM_];
static __device__ __nv_bfloat16 sWqh[(size_t)H_ * KDIM_];
static __device__ __nv_bfloat16 sWql[(size_t)H_ * KDIM_];
static __device__ __nv_bfloat16 sWkh[(size_t)H_ * KDIM_];
static __device__ __nv_bfloat16 sWkl[(size_t)H_ * KDIM_];
static __device__ __nv_bfloat16 sWvh[(size_t)H_ * KDIM_];
static __device__ __nv_bfloat16 sWvl[(size_t)H_ * KDIM_];
static __device__ __nv_bfloat16 sWoh[(size_t)H_ * KDIM_];
static __device__ __nv_bfloat16 sWol[(size_t)H_ * KDIM_];

// attention operands: PLAIN fp16 (11-bit mantissa; 1 MMA per fragment pair)
static __device__ __half sQf[(size_t)B_ * NH_ * S_ * HD_];
static __device__ __half sKf[(size_t)B_ * NH_ * KV_ * HD_];
static __device__ __half sVf[(size_t)B_ * NH_ * KV_ * HD_];
// attention output splits (bf16 h/l for the 3-term output projection)
static __device__ __nv_bfloat16 sAh[(size_t)M_ * KDIM_];
static __device__ __nv_bfloat16 sAl[(size_t)M_ * KDIM_];

// ---------------- helpers ----------------
__device__ __forceinline__ uint32_t smem_u32(const void* p) {
    uint32_t a;
    asm("{ .reg .u64 t; cvta.to.shared.u64 t, %1; cvt.u32.u64 %0, t; }" : "=r"(a) : "l"(p));
    return a;
}

#define LDSM4(r0,r1,r2,r3,addr) \
    asm volatile("ldmatrix.sync.aligned.m8n8.x4.shared.b16 {%0,%1,%2,%3}, [%4];" \
        : "=r"(r0),"=r"(r1),"=r"(r2),"=r"(r3) : "r"(addr))

#define LDSM4T(r0,r1,r2,r3,addr) \
    asm volatile("ldmatrix.sync.aligned.m8n8.x4.trans.shared.b16 {%0,%1,%2,%3}, [%4];" \
        : "=r"(r0),"=r"(r1),"=r"(r2),"=r"(r3) : "r"(addr))

#define MMA16816(c, a, b) \
    asm volatile("mma.sync.aligned.m16n8k16.row.col.f32.bf16.bf16.f32 " \
        "{%0,%1,%2,%3}, {%4,%5,%6,%7}, {%8,%9}, {%0,%1,%2,%3};" \
        : "+f"((c)[0]),"+f"((c)[1]),"+f"((c)[2]),"+f"((c)[3]) \
        : "r"((a)[0]),"r"((a)[1]),"r"((a)[2]),"r"((a)[3]), "r"((b)[0]),"r"((b)[1]))

#define MMA16816H(c, a, b) \
    asm volatile("mma.sync.aligned.m16n8k16.row.col.f32.f16.f16.f32 " \
        "{%0,%1,%2,%3}, {%4,%5,%6,%7}, {%8,%9}, {%0,%1,%2,%3};" \
        : "+f"((c)[0]),"+f"((c)[1]),"+f"((c)[2]),"+f"((c)[3]) \
        : "r"((a)[0]),"r"((a)[1]),"r"((a)[2]),"r"((a)[3]), "r"((b)[0]),"r"((b)[1]))

#define CP_ASYNC16(saddr, gaddr) \
    asm volatile("cp.async.cg.shared.global [%0], [%1], 16;" :: "r"(saddr), "l"(gaddr))
#define CP_COMMIT() asm volatile("cp.async.commit_group;" ::: "memory")
#define CP_WAIT0()  asm volatile("cp.async.wait_group 0;" ::: "memory")

__device__ __forceinline__ void store_split(__nv_bfloat16* dh, __nv_bfloat16* dl,
                                            size_t idx, float2 v) {
    __nv_bfloat16 h0 = __float2bfloat16_rn(v.x), h1 = __float2bfloat16_rn(v.y);
    __nv_bfloat16 l0 = __float2bfloat16_rn(v.x - __bfloat162float(h0));
    __nv_bfloat16 l1 = __float2bfloat16_rn(v.y - __bfloat162float(h1));
    __nv_bfloat162 hh; hh.x = h0; hh.y = h1;
    __nv_bfloat162 ll; ll.x = l0; ll.y = l1;
    *(__nv_bfloat162*)(dh + idx) = hh;
    *(__nv_bfloat162*)(dl + idx) = ll;
}

// ---------------- cache splice (+ fp16 copies for attention) ----------------
__global__ void copy_cache_kernel(const float4* __restrict__ kc,
                                  const float4* __restrict__ vc,
                                  float4* __restrict__ ko,
                                  float4* __restrict__ vo,
                                  uint2* __restrict__ kf, uint2* __restrict__ vf) {
    int i = blockIdx.x * blockDim.x + threadIdx.x;
    int chunk = i >> 16;
    int rem   = i & 65535;
    size_t d = (size_t)chunk * (KV_ * HD_ / 4) + rem;
    float4 kk = kc[i];
    float4 vv = vc[i];
    ko[d] = kk;
    vo[d] = vv;
    __half kh4[4] = {__float2half_rn(kk.x), __float2half_rn(kk.y),
                     __float2half_rn(kk.z), __float2half_rn(kk.w)};
    __half vh4[4] = {__float2half_rn(vv.x), __float2half_rn(vv.y),
                     __float2half_rn(vv.z), __float2half_rn(vv.w)};
    kf[d] = *(uint2*)kh4;
    vf[d] = *(uint2*)vh4;
}

// ---------------- fp32 -> bf16 hi/lo split ----------------
union BF4 { __nv_bfloat16 b[4]; uint2 u; };

__device__ __forceinline__ void split_one(const float4* src, uint2* hi, uint2* lo, int i) {
    float4 v = src[i];
    BF4 H, L;
    float f[4] = {v.x, v.y, v.z, v.w};
    #pragma unroll
    for (int j = 0; j < 4; j++) {
        __nv_bfloat16 h = __float2bfloat16_rn(f[j]);
        H.b[j] = h;
        L.b[j] = __float2bfloat16_rn(f[j] - __bfloat162float(h));
    }
    hi[i] = H.u;
    lo[i] = L.u;
}

__global__ void split_kernel(const float4* __restrict__ src,
                             uint2* __restrict__ hi, uint2* __restrict__ lo) {
    int i = blockIdx.x * blockDim.x + threadIdx.x;
    split_one(src, hi, lo, i);
}

__global__ void split4_kernel(const float4* s0, const float4* s1,
                              const float4* s2, const float4* s3,
                              uint2* h0, uint2* h1, uint2* h2, uint2* h3,
                              uint2* l0, uint2* l1, uint2* l2, uint2* l3) {
    int z = blockIdx.y;
    const float4* s = (z == 0) ? s0 : (z == 1) ? s1 : (z == 2) ? s2 : s3;
    uint2* h = (z == 0) ? h0 : (z == 1) ? h1 : (z == 2) ? h2 : h3;
    uint2* l = (z == 0) ? l0 : (z == 1) ? l1 : (z == 2) ? l2 : l3;
    int i = blockIdx.x * blockDim.x + threadIdx.x;
    split_one(s, h, l, i);
}

// ---------------- mma.sync bf16-split GEMM core (R8-proven: GKC=32, 16 warps) ----------------
// mode 0: fp32 dense dst[row*H_+col]
// mode 1: fp32 scatter (KV layout) + fp16 single to df
// mode 2: fp16 single only, scaled (q)
#define GKC      32
#define GNCH     (KDIM_/GKC)           // 64
#define TPAD     40
#define TILE_B   (128*TPAD*2)          // 10240
#define BUF_B    (4*TILE_B)            // 40960 (Ah,Al,Bh,Bl)
#define GT_SMEM  (512 + 2*BUF_B)       // 82432

__device__ __forceinline__
void gemm_core(const __nv_bfloat16* __restrict__ Ah, const __nv_bfloat16* __restrict__ Al,
               const __nv_bfloat16* __restrict__ Bh, const __nv_bfloat16* __restrict__ Bl,
               const float* __restrict__ bias, float* __restrict__ dst,
               __half* __restrict__ df,
               int mode, int Lrow, int off, float scale,
               char* smc, int m0, int n0)
{
    float* s_bias = (float*)smc;
    const uint32_t sbase = smem_u32(smc + 512);

    const int tid = threadIdx.x;
    const int wid = tid >> 5, lane = tid & 31;
    const int wm = (wid & 3) * 32, wn = (wid >> 2) * 32;

    if (tid < 128) s_bias[tid] = bias[n0 + tid];

    const __nv_bfloat16* srcAh = Ah + (size_t)m0 * KDIM_;
    const __nv_bfloat16* srcAl = Al + (size_t)m0 * KDIM_;
    const __nv_bfloat16* srcBh = Bh + (size_t)n0 * KDIM_;
    const __nv_bfloat16* srcBl = Bl + (size_t)n0 * KDIM_;

    const int ld_row = tid >> 2;          // 0..127
    const int ld_c16 = tid & 3;           // 16B column
    const int aRow = wm + (lane & 15);
    const uint32_t offA0 = ((uint32_t)(aRow * TPAD + ((lane >> 4) << 3))) * 2u;
    const int bRow = wn + ((lane >> 4) << 3) + (lane & 7);
    const uint32_t offB0 = ((uint32_t)(bRow * TPAD + (((lane >> 3) & 1) << 3))) * 2u;

    float acc[2][4][4];
    #pragma unroll
    for (int i = 0; i < 2; i++)
        #pragma unroll
        for (int j = 0; j < 4; j++)
            #pragma unroll
            for (int q = 0; q < 4; q++) acc[i][j][q] = 0.f;

    auto load_chunk = [&](int buf, int c0) {
        uint32_t sb = sbase + buf * BUF_B;
        uint32_t so = (uint32_t)(ld_row * TPAD + ld_c16 * 8) * 2u;
        size_t go = (size_t)ld_row * KDIM_ + c0 + ld_c16 * 8;
        CP_ASYNC16(sb + 0 * TILE_B + so, srcAh + go);
        CP_ASYNC16(sb + 1 * TILE_B + so, srcAl + go);
        CP_ASYNC16(sb + 2 * TILE_B + so, srcBh + go);
        CP_ASYNC16(sb + 3 * TILE_B + so, srcBl + go);
        CP_COMMIT();
    };

    load_chunk(0, 0);

    for (int c = 0; c < GNCH; ++c) {
        CP_WAIT0();
        __syncthreads();
        if (c + 1 < GNCH) load_chunk((c + 1) & 1, (c + 1) * GKC);

        const uint32_t bb = sbase + (c & 1) * BUF_B;
        #pragma unroll
        for (int ks = 0; ks < 2; ++ks) {
            const uint32_t ko_ = ks * 32;
            uint32_t ah[2][4], al[2][4];
            #pragma unroll
            for (int mt = 0; mt < 2; ++mt) {
                LDSM4(ah[mt][0], ah[mt][1], ah[mt][2], ah[mt][3],
                      bb + 0 * TILE_B + offA0 + mt * (16 * TPAD * 2) + ko_);
                LDSM4(al[mt][0], al[mt][1], al[mt][2], al[mt][3],
                      bb + 1 * TILE_B + offA0 + mt * (16 * TPAD * 2) + ko_);
            }
            uint32_t bh[4][2], bl[4][2];
            #pragma unroll
            for (int p = 0; p < 2; ++p) {
                uint32_t r0, r1, r2, r3;
                LDSM4(r0, r1, r2, r3,
                      bb + 2 * TILE_B + offB0 + p * (16 * TPAD * 2) + ko_);
                bh[2*p][0] = r0; bh[2*p][1] = r1; bh[2*p+1][0] = r2; bh[2*p+1][1] = r3;
                LDSM4(r0, r1, r2, r3,
                      bb + 3 * TILE_B + offB0 + p * (16 * TPAD * 2) + ko_);
                bl[2*p][0] = r0; bl[2*p][1] = r1; bl[2*p+1][0] = r2; bl[2*p+1][1] = r3;
            }
            #pragma unroll
            for (int mt = 0; mt < 2; ++mt)
                #pragma unroll
                for (int nt = 0; nt < 4; ++nt) {
                    MMA16816(acc[mt][nt], ah[mt], bh[nt]);
                    MMA16816(acc[mt][nt], ah[mt], bl[nt]);
                    MMA16816(acc[mt][nt], al[mt], bh[nt]);
                }
        }
    }
    __syncthreads();

    #pragma unroll
    for (int mt = 0; mt < 2; ++mt) {
        #pragma unroll
        for (int nt = 0; nt < 4; ++nt) {
            float* cc = acc[mt][nt];
            int row0 = m0 + wm + mt * 16 + (lane >> 2);
            int col  = wn + nt * 8 + (lane & 3) * 2;
            float2 v0 = make_float2((cc[0] + s_bias[col]) * scale,
                                    (cc[1] + s_bias[col + 1]) * scale);
            float2 v1 = make_float2((cc[2] + s_bias[col]) * scale,
                                    (cc[3] + s_bias[col + 1]) * scale);
            if (mode == 0) {
                float* p0 = dst + (size_t)row0 * H_ + n0 + col;
                *(float2*)p0 = v0;
                *(float2*)(p0 + (size_t)8 * H_) = v1;
            } else {
                int bb_ = row0 >> 11, s = row0 & (S_ - 1);
                int head = n0 >> 7;
                size_t idx = ((size_t)(bb_ * NH_ + head) * Lrow + off + s) * HD_ + (col & (HD_ - 1));
                size_t idx1 = idx + (size_t)8 * HD_;
                if (mode == 1) {
                    *(float2*)(dst + idx)  = v0;
                    *(float2*)(dst + idx1) = v1;
                }
                *(__half2*)(df + idx)  = __floats2half2_rn(v0.x, v0.y);
                *(__half2*)(df + idx1) = __floats2half2_rn(v1.x, v1.y);
            }
        }
    }
}

__global__ __launch_bounds__(512, 1)
void gemm_qkv(const __nv_bfloat16* __restrict__ xh, const __nv_bfloat16* __restrict__ xl,
              const __nv_bfloat16* __restrict__ wqh, const __nv_bfloat16* __restrict__ wql,
              const __nv_bfloat16* __restrict__ wkh, const __nv_bfloat16* __restrict__ wkl,
              const __nv_bfloat16* __restrict__ wvh, const __nv_bfloat16* __restrict__ wvl,
              const float* __restrict__ bq, const float* __restrict__ bk,
              const float* __restrict__ bv,
              float* __restrict__ ko, float* __restrict__ vo,
              __half* __restrict__ qf, __half* __restrict__ kf, __half* __restrict__ vf)
{
    extern __shared__ char smc[];
    const int z = blockIdx.z;
    const int n0 = blockIdx.x * 128, m0 = blockIdx.y * 128;
    if (z == 0) {
        gemm_core(xh, xl, wqh, wql, bq, nullptr, qf, 2, S_, 0, SCALE_, smc, m0, n0);
    } else if (z == 1) {
        gemm_core(xh, xl, wkh, wkl, bk, ko, kf, 1, KV_, CACHE_, 1.0f, smc, m0, n0);
    } else {
        gemm_core(xh, xl, wvh, wvl, bv, vo, vf, 1, KV_, CACHE_, 1.0f, smc, m0, n0);
    }
}

__global__ __launch_bounds__(512, 1)
void gemm_out(const __nv_bfloat16* __restrict__ Ah, const __nv_bfloat16* __restrict__ Al,
              const __nv_bfloat16* __restrict__ Bh, const __nv_bfloat16* __restrict__ Bl,
              const float* __restrict__ bias, float* __restrict__ dst)
{
    extern __shared__ char smc[];
    gemm_core(Ah, Al, Bh, Bl, bias, dst, nullptr, 0, 0, 0, 1.0f,
              smc, blockIdx.y * 128, blockIdx.x * 128);
}

// ---------------- flash attention via mma.sync, PLAIN fp16 operands ----------------
// R14: Q/K/V/P in fp16 single precision (11-bit mantissa): 64 MMAs/iter vs 192.
// Geometry/softmax/ballot-skip byte-identical to R11. Softmax stays fp32.
#define AKT 32
#define QPITCH 272
#define KOFF   0
#define VOFF   8704
#define MSOFF  17408
#define STAGE_B 33792                    // K 8704 + V 8704 + mask 16384
#define QBYTES (128*QPITCH)              // 34816 (single fp16 copy)
#define QOFF   (2*STAGE_B)               // 67584
#define ATT_SMEM (2*STAGE_B + QBYTES)    // 102400

__global__ __launch_bounds__(256, 1)
void attn_mma(const __half* __restrict__ Qf,
              const __half* __restrict__ Kf,
              const __half* __restrict__ Vf,
              const float* __restrict__ Msk,
              __nv_bfloat16* __restrict__ Oh, __nv_bfloat16* __restrict__ Ol)
{
    extern __shared__ char sma[];
    const uint32_t sb = smem_u32(sma);

    const int tid = threadIdx.x;
    const int wid = tid >> 5, lane = tid & 31;
    const int qt = blockIdx.x, h = blockIdx.y, b = blockIdx.z;

    const size_t bh_q = ((size_t)(b * NH_ + h) * S_ + qt * 128) * HD_;
    const size_t bh_kv = (size_t)(b * NH_ + h) * KV_ * HD_;
    const float* Mb = Msk + ((size_t)b * S_ + qt * 128) * KV_;

    // --- Q cp.async (single fp16 copy) ---
    {
        int qr = tid >> 1, qc = (tid & 1) * 8;
        const __half* qp = Qf + bh_q + (size_t)qr * HD_ + qc * 8;
        uint32_t d0 = sb + QOFF + qr * QPITCH + qc * 16;
        #pragma unroll
        for (int j = 0; j < 8; j++)
            CP_ASYNC16(d0 + j * 16, qp + j * 8);
    }
    const int kv_row = tid >> 3, kv_c = tid & 7;
    const int m_row = tid >> 1, m_c = (tid & 1) * 4;
    auto issue_stage = [&](int t) {
        uint32_t st = sb + (t & 1) * STAGE_B;
        size_t go = bh_kv + (size_t)(t * AKT + kv_row) * HD_ + kv_c * 8;
        uint32_t so = st + kv_row * QPITCH + kv_c * 16;
        CP_ASYNC16(so + KOFF,       Kf + go);
        CP_ASYNC16(so + KOFF + 128, Kf + go + 64);
        CP_ASYNC16(so + VOFF,       Vf + go);
        CP_ASYNC16(so + VOFF + 128, Vf + go + 64);
        const float* mp = Mb + (size_t)m_row * KV_ + t * AKT + m_c * 4;
        uint32_t md = st + MSOFF + m_row * 128 + m_c * 16;
        #pragma unroll
        for (int j = 0; j < 4; j++)
            CP_ASYNC16(md + j * 16, mp + j * 4);
    };
    issue_stage(0);
    CP_COMMIT();

    uint32_t qF[8][4];
    float o[16][4];
    #pragma unroll
    for (int i = 0; i < 16; i++)
        #pragma unroll
        for (int j = 0; j < 4; j++) o[i][j] = 0.f;
    float m0r = -1e30f, m1r = -1e30f, l0r = 0.f, l1r = 0.f;

    const uint32_t qAoff = (uint32_t)((wid * 16 + (lane & 15)) * QPITCH + ((lane >> 4) << 3) * 2);
    const uint32_t kBrow = (uint32_t)((((lane >> 4) << 3) + (lane & 7)) * QPITCH + (((lane >> 3) & 1) << 3) * 2);
    const uint32_t vTrow = (uint32_t)(((((lane >> 3) & 1) << 3) + (lane & 7)) * QPITCH + ((lane >> 4) << 3) * 2);

    const int NIT = KV_ / AKT;   // 128
    for (int t = 0; t < NIT; ++t) {
        CP_WAIT0();
        __syncthreads();
        if (t + 1 < NIT) { issue_stage(t + 1); CP_COMMIT(); }

        if (t == 0) {
            #pragma unroll
            for (int ks = 0; ks < 8; ++ks)
                LDSM4(qF[ks][0], qF[ks][1], qF[ks][2], qF[ks][3], sb + QOFF + qAoff + ks * 32);
        }

        const uint32_t st = sb + (t & 1) * STAGE_B;

        // ---- scores (fp16 single: 2 MMAs per k-fragment group) ----
        float sacc[4][4];
        #pragma unroll
        for (int i = 0; i < 4; i++)
            #pragma unroll
            for (int j = 0; j < 4; j++) sacc[i][j] = 0.f;

        #pragma unroll
        for (int ks = 0; ks < 8; ++ks) {
            #pragma unroll
            for (int nh = 0; nh < 2; ++nh) {
                uint32_t k0, k1, k2, k3;
                LDSM4(k0, k1, k2, k3,
                      st + KOFF + kBrow + nh * 16 * QPITCH + ks * 32);
                uint32_t b0[2] = {k0, k1}, b1[2] = {k2, k3};
                MMA16816H(sacc[2*nh],   qF[ks], b0);
                MMA16816H(sacc[2*nh+1], qF[ks], b1);
            }
        }

        // ---- softmax (fp32; q pre-scaled; add mask) ----
        const uint32_t msb = st + MSOFF + (wid * 16 + (lane >> 2)) * 128 + (lane & 3) * 8;
        float p[4][4];
        float rm0 = -1e30f, rm1 = -1e30f;
        #pragma unroll
        for (int nt = 0; nt < 4; ++nt) {
            float2 mv0 = *(const float2*)(sma + (msb + nt * 32 - sb));
            float2 mv1 = *(const float2*)(sma + (msb + nt * 32 + 8 * 128 - sb));
            p[nt][0] = sacc[nt][0] + mv0.x;
            p[nt][1] = sacc[nt][1] + mv0.y;
            p[nt][2] = sacc[nt][2] + mv1.x;
            p[nt][3] = sacc[nt][3] + mv1.y;
            rm0 = fmaxf(rm0, fmaxf(p[nt][0], p[nt][1]));
            rm1 = fmaxf(rm1, fmaxf(p[nt][2], p[nt][3]));
        }
        rm0 = fmaxf(rm0, __shfl_xor_sync(0xffffffffu, rm0, 1));
        rm0 = fmaxf(rm0, __shfl_xor_sync(0xffffffffu, rm0, 2));
        rm1 = fmaxf(rm1, __shfl_xor_sync(0xffffffffu, rm1, 1));
        rm1 = fmaxf(rm1, __shfl_xor_sync(0xffffffffu, rm1, 2));
        float nm0 = fmaxf(m0r, rm0), nm1 = fmaxf(m1r, rm1);

        float rs0 = 0.f, rs1 = 0.f;
        #pragma unroll
        for (int nt = 0; nt < 4; ++nt) {
            p[nt][0] = __expf(p[nt][0] - nm0);
            p[nt][1] = __expf(p[nt][1] - nm0);
            p[nt][2] = __expf(p[nt][2] - nm1);
            p[nt][3] = __expf(p[nt][3] - nm1);
            rs0 += p[nt][0] + p[nt][1];
            rs1 += p[nt][2] + p[nt][3];
        }
        rs0 += __shfl_xor_sync(0xffffffffu, rs0, 1);
        rs0 += __shfl_xor_sync(0xffffffffu, rs0, 2);
        rs1 += __shfl_xor_sync(0xffffffffu, rs1, 1);
        rs1 += __shfl_xor_sync(0xffffffffu, rs1, 2);

        // ballot-skip rescale: alpha==1 exactly when max unchanged
        uint32_t need = __ballot_sync(0xffffffffu, (nm0 > m0r) || (nm1 > m1r));
        if (need) {
            float al0 = __expf(m0r - nm0), al1 = __expf(m1r - nm1);
            #pragma unroll
            for (int i = 0; i < 16; i++) {
                o[i][0] *= al0; o[i][1] *= al0;
                o[i][2] *= al1; o[i][3] *= al1;
            }
            l0r = l0r * al0 + rs0;
            l1r = l1r * al1 + rs1;
        } else {
            l0r += rs0;
            l1r += rs1;
        }
        m0r = nm0; m1r = nm1;

        // ---- P -> fp16 A-frags ----
        uint32_t pF[2][4];
        #pragma unroll
        for (int ks2 = 0; ks2 < 2; ++ks2) {
            #pragma unroll
            for (int half = 0; half < 2; ++half) {
                int nt = 2 * ks2 + half;
                #pragma unroll
                for (int rr = 0; rr < 2; ++rr) {
                    __half2 hp = __floats2half2_rn(p[nt][2*rr], p[nt][2*rr+1]);
                    pF[ks2][half*2 + rr] = *(uint32_t*)&hp;
                }
            }
        }

        // ---- PV (fp16 single) ----
        #pragma unroll
        for (int ks2 = 0; ks2 < 2; ++ks2) {
            #pragma unroll
            for (int vb = 0; vb < 8; ++vb) {
                uint32_t h0, h1, h2, h3;
                LDSM4T(h0, h1, h2, h3,
                       st + VOFF + vTrow + ks2 * 16 * QPITCH + vb * 32);
                uint32_t b0[2] = {h0, h1}, b1[2] = {h2, h3};
                MMA16816H(o[2*vb],   pF[ks2], b0);
                MMA16816H(o[2*vb+1], pF[ks2], b1);
            }
        }
    }

    float i0 = 1.0f / l0r, i1 = 1.0f / l1r;
    int r0 = qt * 128 + wid * 16 + (lane >> 2);
    size_t base0 = ((size_t)b * S_ + r0) * H_ + h * HD_ + (lane & 3) * 2;
    size_t base1 = base0 + (size_t)8 * H_;
    #pragma unroll
    for (int nt = 0; nt < 16; ++nt) {
        store_split(Oh, Ol, base0 + nt * 8, make_float2(o[nt][0] * i0, o[nt][1] * i0));
        store_split(Oh, Ol, base1 + nt * 8, make_float2(o[nt][2] * i1, o[nt][3] * i1));
    }
}

// ---------------- launch ----------------
extern "C" void kernel_launch(void* const* d_in, const int* in_sizes, int n_in,
                              void* d_out, int out_size) {
    (void)in_sizes; (void)n_in; (void)out_size;
    const float* x   = (const float*)d_in[0];
    const float* msk = (const float*)d_in[1];
    const float* kc  = (const float*)d_in[2];
    const float* vc  = (const float*)d_in[3];
    const float* Wq  = (const float*)d_in[4];
    const float* bq  = (const float*)d_in[5];
    const float* Wk  = (const float*)d_in[6];
    const float* bk  = (const float*)d_in[7];
    const float* Wv  = (const float*)d_in[8];
    const float* bv  = (const float*)d_in[9];
    const float* Wo  = (const float*)d_in[10];
    const float* bo  = (const float*)d_in[11];

    float* out = (float*)d_out;
    float* ko  = out + (size_t)B_ * S_ * H_;
    float* vo  = ko  + (size_t)B_ * NH_ * KV_ * HD_;

    __nv_bfloat16 *xh, *xl, *wqh, *wql, *wkh, *wkl, *wvh, *wvl, *woh, *wol, *ah, *al;
    __half *qf, *kf, *vf;
    cudaGetSymbolAddress((void**)&xh,  sXh);  cudaGetSymbolAddress((void**)&xl,  sXl);
    cudaGetSymbolAddress((void**)&wqh, sWqh); cudaGetSymbolAddress((void**)&wql, sWql);
    cudaGetSymbolAddress((void**)&wkh, sWkh); cudaGetSymbolAddress((void**)&wkl, sWkl);
    cudaGetSymbolAddress((void**)&wvh, sWvh); cudaGetSymbolAddress((void**)&wvl, sWvl);
    cudaGetSymbolAddress((void**)&woh, sWoh); cudaGetSymbolAddress((void**)&wol, sWol);
    cudaGetSymbolAddress((void**)&qf, sQf); cudaGetSymbolAddress((void**)&kf, sKf);
    cudaGetSymbolAddress((void**)&vf, sVf);
    cudaGetSymbolAddress((void**)&ah, sAh); cudaGetSymbolAddress((void**)&al, sAl);

    cudaFuncSetAttribute(gemm_qkv,
                         cudaFuncAttributeMaxDynamicSharedMemorySize, GT_SMEM);
    cudaFuncSetAttribute(gemm_out,
                         cudaFuncAttributeMaxDynamicSharedMemorySize, GT_SMEM);
    cudaFuncSetAttribute(attn_mma,
                         cudaFuncAttributeMaxDynamicSharedMemorySize, ATT_SMEM);

    // 1. splice caches into output k/v (+ fp16 copies for attention)
    copy_cache_kernel<<<8192, 256>>>((const float4*)kc, (const float4*)vc,
                                     (float4*)ko, (float4*)vo,
                                     (uint2*)kf, (uint2*)vf);

    // 2. bf16 hi/lo splits of inputs (GEMMs keep 3-term accuracy)
    split_kernel<<<8192, 256>>>((const float4*)x, (uint2*)xh, (uint2*)xl);
    split4_kernel<<<dim3(4096, 4), 256>>>(
        (const float4*)Wq, (const float4*)Wk, (const float4*)Wv, (const float4*)Wo,
        (uint2*)wqh, (uint2*)wkh, (uint2*)wvh, (uint2*)woh,
        (uint2*)wql, (uint2*)wkl, (uint2*)wvl, (uint2*)wol);

    // 3. fused QKV projections (bf16 3-term); epilogues emit fp16 q/k/v
    gemm_qkv<<<dim3(H_/128, M_/128, 3), 512, GT_SMEM>>>(
        xh, xl, wqh, wql, wkh, wkl, wvh, wvl, bq, bk, bv,
        ko, vo, qf, kf, vf);

    // 4. attention (fp16 operands, fp32 softmax); emits bf16 output splits
    attn_mma<<<dim3(S_/128, NH_, B_), 256, ATT_SMEM>>>(qf, kf, vf, msk, ah, al);

    // 5. output projection (bf16 3-term)
    gemm_out<<<dim3(H_/128, M_/128), 512, GT_SMEM>>>(ah, al, woh, wol, bo, out);
}

// round 15
// speedup vs baseline: 1.5710x; 1.2242x over previous
#include <cuda_runtime.h>
#include <cuda_bf16.h>
#include <cuda_fp16.h>
#include <cstdint>

// ---------------- problem constants ----------------
#define B_     2
#define S_     2048
#define H_     2048
#define NH_    16
#define HD_    128
#define CACHE_ 2048
#define KV_    4096           // CACHE_ + S_
#define M_     4096           // B_*S_
#define KDIM_  2048           // H_

#define SCALE_ 0.08838834764831845f   // 1/sqrt(128)

// fp16 scratch (allocation-free rule: __device__ globals)
// activations: 2-term fp16 split (hi + lo); weights: plain fp16
static __device__ __half sXh[(size_t)M_ * KDIM_];
static __device__ __half sXl[(size_t)M_ * KDIM_];
static __device__ __half sWq[(size_t)H_ * KDIM_];
static __device__ __half sWk[(size_t)H_ * KDIM_];
static __device__ __half sWv[(size_t)H_ * KDIM_];
static __device__ __half sWo[(size_t)H_ * KDIM_];

// attention operands: plain fp16
static __device__ __half sQf[(size_t)B_ * NH_ * S_ * HD_];
static __device__ __half sKf[(size_t)B_ * NH_ * KV_ * HD_];
static __device__ __half sVf[(size_t)B_ * NH_ * KV_ * HD_];
// attention output: fp16 2-term split for the output projection
static __device__ __half sAh[(size_t)M_ * KDIM_];
static __device__ __half sAl[(size_t)M_ * KDIM_];

// ---------------- helpers ----------------
__device__ __forceinline__ uint32_t smem_u32(const void* p) {
    uint32_t a;
    asm("{ .reg .u64 t; cvta.to.shared.u64 t, %1; cvt.u32.u64 %0, t; }" : "=r"(a) : "l"(p));
    return a;
}

#define LDSM4(r0,r1,r2,r3,addr) \
    asm volatile("ldmatrix.sync.aligned.m8n8.x4.shared.b16 {%0,%1,%2,%3}, [%4];" \
        : "=r"(r0),"=r"(r1),"=r"(r2),"=r"(r3) : "r"(addr))

#define LDSM4T(r0,r1,r2,r3,addr) \
    asm volatile("ldmatrix.sync.aligned.m8n8.x4.trans.shared.b16 {%0,%1,%2,%3}, [%4];" \
        : "=r"(r0),"=r"(r1),"=r"(r2),"=r"(r3) : "r"(addr))

#define MMA16816H(c, a, b) \
    asm volatile("mma.sync.aligned.m16n8k16.row.col.f32.f16.f16.f32 " \
        "{%0,%1,%2,%3}, {%4,%5,%6,%7}, {%8,%9}, {%0,%1,%2,%3};" \
        : "+f"((c)[0]),"+f"((c)[1]),"+f"((c)[2]),"+f"((c)[3]) \
        : "r"((a)[0]),"r"((a)[1]),"r"((a)[2]),"r"((a)[3]), "r"((b)[0]),"r"((b)[1]))

#define CP_ASYNC16(saddr, gaddr) \
    asm volatile("cp.async.cg.shared.global [%0], [%1], 16;" :: "r"(saddr), "l"(gaddr))
#define CP_COMMIT() asm volatile("cp.async.commit_group;" ::: "memory")
#define CP_WAIT0()  asm volatile("cp.async.wait_group 0;" ::: "memory")

__device__ __forceinline__ void store_split_h(__half* dh, __half* dl,
                                              size_t idx, float2 v) {
    __half h0 = __float2half_rn(v.x), h1 = __float2half_rn(v.y);
    __half l0 = __float2half_rn(v.x - __half2float(h0));
    __half l1 = __float2half_rn(v.y - __half2float(h1));
    __half2 hh; hh.x = h0; hh.y = h1;
    __half2 ll; ll.x = l0; ll.y = l1;
    *(__half2*)(dh + idx) = hh;
    *(__half2*)(dl + idx) = ll;
}

// ---------------- cache splice (+ fp16 copies for attention) ----------------
__global__ void copy_cache_kernel(const float4* __restrict__ kc,
                                  const float4* __restrict__ vc,
                                  float4* __restrict__ ko,
                                  float4* __restrict__ vo,
                                  uint2* __restrict__ kf, uint2* __restrict__ vf) {
    int i = blockIdx.x * blockDim.x + threadIdx.x;
    int chunk = i >> 16;
    int rem   = i & 65535;
    size_t d = (size_t)chunk * (KV_ * HD_ / 4) + rem;
    float4 kk = kc[i];
    float4 vv = vc[i];
    ko[d] = kk;
    vo[d] = vv;
    __half kh4[4] = {__float2half_rn(kk.x), __float2half_rn(kk.y),
                     __float2half_rn(kk.z), __float2half_rn(kk.w)};
    __half vh4[4] = {__float2half_rn(vv.x), __float2half_rn(vv.y),
                     __float2half_rn(vv.z), __float2half_rn(vv.w)};
    kf[d] = *(uint2*)kh4;
    vf[d] = *(uint2*)vh4;
}

// ---------------- fp32 -> fp16 hi/lo split (activations) ----------------
__global__ void split_h_kernel(const float4* __restrict__ src,
                               uint2* __restrict__ hi, uint2* __restrict__ lo) {
    int i = blockIdx.x * blockDim.x + threadIdx.x;
    float4 v = src[i];
    float f[4] = {v.x, v.y, v.z, v.w};
    __half H[4], L[4];
    #pragma unroll
    for (int j = 0; j < 4; j++) {
        H[j] = __float2half_rn(f[j]);
        L[j] = __float2half_rn(f[j] - __half2float(H[j]));
    }
    hi[i] = *(uint2*)H;
    lo[i] = *(uint2*)L;
}

// fused 4-weight fp32 -> plain fp16 convert
__global__ void convert4_kernel(const float4* s0, const float4* s1,
                                const float4* s2, const float4* s3,
                                uint2* d0, uint2* d1, uint2* d2, uint2* d3) {
    int z = blockIdx.y;
    const float4* s = (z == 0) ? s0 : (z == 1) ? s1 : (z == 2) ? s2 : s3;
    uint2* d = (z == 0) ? d0 : (z == 1) ? d1 : (z == 2) ? d2 : d3;
    int i = blockIdx.x * blockDim.x + threadIdx.x;
    float4 v = s[i];
    __half h[4] = {__float2half_rn(v.x), __float2half_rn(v.y),
                   __float2half_rn(v.z), __float2half_rn(v.w)};
    d[i] = *(uint2*)h;
}

// ---------------- mma.sync fp16 GEMM core ----------------
// D = (Ah + Al)[M,K] x B[N,K]^T + bias   (A 2-term fp16 split, B plain fp16)
// 2 MMAs per fragment pair (was 3 bf16). R8-proven geometry otherwise:
// GKC=32, 16 warps (512 thr), warp tile 32x32, TPAD=40, double-buffered.
// mode 0: fp32 dense; mode 1: fp32 KV scatter + fp16 to df; mode 2: fp16 scaled (q)
#define GKC      32
#define GNCH     (KDIM_/GKC)           // 64
#define TPAD     40
#define TILE_B   (128*TPAD*2)          // 10240
#define BUF_B    (3*TILE_B)            // 30720 (Ah,Al,B)
#define GT_SMEM  (512 + 2*BUF_B)       // 61952

__device__ __forceinline__
void gemm_core(const __half* __restrict__ Ah, const __half* __restrict__ Al,
               const __half* __restrict__ Bf,
               const float* __restrict__ bias, float* __restrict__ dst,
               __half* __restrict__ df,
               int mode, int Lrow, int off, float scale,
               char* smc, int m0, int n0)
{
    float* s_bias = (float*)smc;
    const uint32_t sbase = smem_u32(smc + 512);

    const int tid = threadIdx.x;
    const int wid = tid >> 5, lane = tid & 31;
    const int wm = (wid & 3) * 32, wn = (wid >> 2) * 32;

    if (tid < 128) s_bias[tid] = bias[n0 + tid];

    const __half* srcAh = Ah + (size_t)m0 * KDIM_;
    const __half* srcAl = Al + (size_t)m0 * KDIM_;
    const __half* srcB  = Bf + (size_t)n0 * KDIM_;

    const int ld_row = tid >> 2;          // 0..127
    const int ld_c16 = tid & 3;           // 16B column
    const int aRow = wm + (lane & 15);
    const uint32_t offA0 = ((uint32_t)(aRow * TPAD + ((lane >> 4) << 3))) * 2u;
    const int bRow = wn + ((lane >> 4) << 3) + (lane & 7);
    const uint32_t offB0 = ((uint32_t)(bRow * TPAD + (((lane >> 3) & 1) << 3))) * 2u;

    float acc[2][4][4];
    #pragma unroll
    for (int i = 0; i < 2; i++)
        #pragma unroll
        for (int j = 0; j < 4; j++)
            #pragma unroll
            for (int q = 0; q < 4; q++) acc[i][j][q] = 0.f;

    auto load_chunk = [&](int buf, int c0) {
        uint32_t sb = sbase + buf * BUF_B;
        uint32_t so = (uint32_t)(ld_row * TPAD + ld_c16 * 8) * 2u;
        size_t go = (size_t)ld_row * KDIM_ + c0 + ld_c16 * 8;
        CP_ASYNC16(sb + 0 * TILE_B + so, srcAh + go);
        CP_ASYNC16(sb + 1 * TILE_B + so, srcAl + go);
        CP_ASYNC16(sb + 2 * TILE_B + so, srcB  + go);
        CP_COMMIT();
    };

    load_chunk(0, 0);

    for (int c = 0; c < GNCH; ++c) {
        CP_WAIT0();
        __syncthreads();
        if (c + 1 < GNCH) load_chunk((c + 1) & 1, (c + 1) * GKC);

        const uint32_t bb = sbase + (c & 1) * BUF_B;
        #pragma unroll
        for (int ks = 0; ks < 2; ++ks) {
            const uint32_t ko_ = ks * 32;
            uint32_t ah[2][4], al[2][4];
            #pragma unroll
            for (int mt = 0; mt < 2; ++mt) {
                LDSM4(ah[mt][0], ah[mt][1], ah[mt][2], ah[mt][3],
                      bb + 0 * TILE_B + offA0 + mt * (16 * TPAD * 2) + ko_);
                LDSM4(al[mt][0], al[mt][1], al[mt][2], al[mt][3],
                      bb + 1 * TILE_B + offA0 + mt * (16 * TPAD * 2) + ko_);
            }
            uint32_t bf[4][2];
            #pragma unroll
            for (int p = 0; p < 2; ++p) {
                uint32_t r0, r1, r2, r3;
                LDSM4(r0, r1, r2, r3,
                      bb + 2 * TILE_B + offB0 + p * (16 * TPAD * 2) + ko_);
                bf[2*p][0] = r0; bf[2*p][1] = r1; bf[2*p+1][0] = r2; bf[2*p+1][1] = r3;
            }
            #pragma unroll
            for (int mt = 0; mt < 2; ++mt)
                #pragma unroll
                for (int nt = 0; nt < 4; ++nt) {
                    MMA16816H(acc[mt][nt], ah[mt], bf[nt]);
                    MMA16816H(acc[mt][nt], al[mt], bf[nt]);
                }
        }
    }
    __syncthreads();

    #pragma unroll
    for (int mt = 0; mt < 2; ++mt) {
        #pragma unroll
        for (int nt = 0; nt < 4; ++nt) {
            float* cc = acc[mt][nt];
            int row0 = m0 + wm + mt * 16 + (lane >> 2);
            int col  = wn + nt * 8 + (lane & 3) * 2;
            float2 v0 = make_float2((cc[0] + s_bias[col]) * scale,
                                    (cc[1] + s_bias[col + 1]) * scale);
            float2 v1 = make_float2((cc[2] + s_bias[col]) * scale,
                                    (cc[3] + s_bias[col + 1]) * scale);
            if (mode == 0) {
                float* p0 = dst + (size_t)row0 * H_ + n0 + col;
                *(float2*)p0 = v0;
                *(float2*)(p0 + (size_t)8 * H_) = v1;
            } else {
                int bb_ = row0 >> 11, s = row0 & (S_ - 1);
                int head = n0 >> 7;
                size_t idx = ((size_t)(bb_ * NH_ + head) * Lrow + off + s) * HD_ + (col & (HD_ - 1));
                size_t idx1 = idx + (size_t)8 * HD_;
                if (mode == 1) {
                    *(float2*)(dst + idx)  = v0;
                    *(float2*)(dst + idx1) = v1;
                }
                *(__half2*)(df + idx)  = __floats2half2_rn(v0.x, v0.y);
                *(__half2*)(df + idx1) = __floats2half2_rn(v1.x, v1.y);
            }
        }
    }
}

__global__ __launch_bounds__(512, 1)
void gemm_qkv(const __half* __restrict__ xh, const __half* __restrict__ xl,
              const __half* __restrict__ wq, const __half* __restrict__ wk,
              const __half* __restrict__ wv,
              const float* __restrict__ bq, const float* __restrict__ bk,
              const float* __restrict__ bv,
              float* __restrict__ ko, float* __restrict__ vo,
              __half* __restrict__ qf, __half* __restrict__ kf, __half* __restrict__ vf)
{
    extern __shared__ char smc[];
    const int z = blockIdx.z;
    const int n0 = blockIdx.x * 128, m0 = blockIdx.y * 128;
    if (z == 0) {
        gemm_core(xh, xl, wq, bq, nullptr, qf, 2, S_, 0, SCALE_, smc, m0, n0);
    } else if (z == 1) {
        gemm_core(xh, xl, wk, bk, ko, kf, 1, KV_, CACHE_, 1.0f, smc, m0, n0);
    } else {
        gemm_core(xh, xl, wv, bv, vo, vf, 1, KV_, CACHE_, 1.0f, smc, m0, n0);
    }
}

__global__ __launch_bounds__(512, 1)
void gemm_out(const __half* __restrict__ Ah, const __half* __restrict__ Al,
              const __half* __restrict__ Bf,
              const float* __restrict__ bias, float* __restrict__ dst)
{
    extern __shared__ char smc[];
    gemm_core(Ah, Al, Bf, bias, dst, nullptr, 0, 0, 0, 1.0f,
              smc, blockIdx.y * 128, blockIdx.x * 128);
}

// ---------------- flash attention via mma.sync, plain fp16 operands ----------------
// R14-proven: fp16 Q/K/V/P, fp32 softmax, ballot-skip rescale. Epilogue now
// writes fp16 hi/lo splits for the fp16 output projection.
#define AKT 32
#define QPITCH 272
#define KOFF   0
#define VOFF   8704
#define MSOFF  17408
#define STAGE_B 33792
#define QBYTES (128*QPITCH)
#define QOFF   (2*STAGE_B)
#define ATT_SMEM (2*STAGE_B + QBYTES)    // 102400

__global__ __launch_bounds__(256, 1)
void attn_mma(const __half* __restrict__ Qf,
              const __half* __restrict__ Kf,
              const __half* __restrict__ Vf,
              const float* __restrict__ Msk,
              __half* __restrict__ Oh, __half* __restrict__ Ol)
{
    extern __shared__ char sma[];
    const uint32_t sb = smem_u32(sma);

    const int tid = threadIdx.x;
    const int wid = tid >> 5, lane = tid & 31;
    const int qt = blockIdx.x, h = blockIdx.y, b = blockIdx.z;

    const size_t bh_q = ((size_t)(b * NH_ + h) * S_ + qt * 128) * HD_;
    const size_t bh_kv = (size_t)(b * NH_ + h) * KV_ * HD_;
    const float* Mb = Msk + ((size_t)b * S_ + qt * 128) * KV_;

    {
        int qr = tid >> 1, qc = (tid & 1) * 8;
        const __half* qp = Qf + bh_q + (size_t)qr * HD_ + qc * 8;
        uint32_t d0 = sb + QOFF + qr * QPITCH + qc * 16;
        #pragma unroll
        for (int j = 0; j < 8; j++)
            CP_ASYNC16(d0 + j * 16, qp + j * 8);
    }
    const int kv_row = tid >> 3, kv_c = tid & 7;
    const int m_row = tid >> 1, m_c = (tid & 1) * 4;
    auto issue_stage = [&](int t) {
        uint32_t st = sb + (t & 1) * STAGE_B;
        size_t go = bh_kv + (size_t)(t * AKT + kv_row) * HD_ + kv_c * 8;
        uint32_t so = st + kv_row * QPITCH + kv_c * 16;
        CP_ASYNC16(so + KOFF,       Kf + go);
        CP_ASYNC16(so + KOFF + 128, Kf + go + 64);
        CP_ASYNC16(so + VOFF,       Vf + go);
        CP_ASYNC16(so + VOFF + 128, Vf + go + 64);
        const float* mp = Mb + (size_t)m_row * KV_ + t * AKT + m_c * 4;
        uint32_t md = st + MSOFF + m_row * 128 + m_c * 16;
        #pragma unroll
        for (int j = 0; j < 4; j++)
            CP_ASYNC16(md + j * 16, mp + j * 4);
    };
    issue_stage(0);
    CP_COMMIT();

    uint32_t qF[8][4];
    float o[16][4];
    #pragma unroll
    for (int i = 0; i < 16; i++)
        #pragma unroll
        for (int j = 0; j < 4; j++) o[i][j] = 0.f;
    float m0r = -1e30f, m1r = -1e30f, l0r = 0.f, l1r = 0.f;

    const uint32_t qAoff = (uint32_t)((wid * 16 + (lane & 15)) * QPITCH + ((lane >> 4) << 3) * 2);
    const uint32_t kBrow = (uint32_t)((((lane >> 4) << 3) + (lane & 7)) * QPITCH + (((lane >> 3) & 1) << 3) * 2);
    const uint32_t vTrow = (uint32_t)(((((lane >> 3) & 1) << 3) + (lane & 7)) * QPITCH + ((lane >> 4) << 3) * 2);

    const int NIT = KV_ / AKT;   // 128
    for (int t = 0; t < NIT; ++t) {
        CP_WAIT0();
        __syncthreads();
        if (t + 1 < NIT) { issue_stage(t + 1); CP_COMMIT(); }

        if (t == 0) {
            #pragma unroll
            for (int ks = 0; ks < 8; ++ks)
                LDSM4(qF[ks][0], qF[ks][1], qF[ks][2], qF[ks][3], sb + QOFF + qAoff + ks * 32);
        }

        const uint32_t st = sb + (t & 1) * STAGE_B;

        float sacc[4][4];
        #pragma unroll
        for (int i = 0; i < 4; i++)
            #pragma unroll
            for (int j = 0; j < 4; j++) sacc[i][j] = 0.f;

        #pragma unroll
        for (int ks = 0; ks < 8; ++ks) {
            #pragma unroll
            for (int nh = 0; nh < 2; ++nh) {
                uint32_t k0, k1, k2, k3;
                LDSM4(k0, k1, k2, k3,
                      st + KOFF + kBrow + nh * 16 * QPITCH + ks * 32);
                uint32_t b0[2] = {k0, k1}, b1[2] = {k2, k3};
                MMA16816H(sacc[2*nh],   qF[ks], b0);
                MMA16816H(sacc[2*nh+1], qF[ks], b1);
            }
        }

        const uint32_t msb = st + MSOFF + (wid * 16 + (lane >> 2)) * 128 + (lane & 3) * 8;
        float p[4][4];
        float rm0 = -1e30f, rm1 = -1e30f;
        #pragma unroll
        for (int nt = 0; nt < 4; ++nt) {
            float2 mv0 = *(const float2*)(sma + (msb + nt * 32 - sb));
            float2 mv1 = *(const float2*)(sma + (msb + nt * 32 + 8 * 128 - sb));
            p[nt][0] = sacc[nt][0] + mv0.x;
            p[nt][1] = sacc[nt][1] + mv0.y;
            p[nt][2] = sacc[nt][2] + mv1.x;
            p[nt][3] = sacc[nt][3] + mv1.y;
            rm0 = fmaxf(rm0, fmaxf(p[nt][0], p[nt][1]));
            rm1 = fmaxf(rm1, fmaxf(p[nt][2], p[nt][3]));
        }
        rm0 = fmaxf(rm0, __shfl_xor_sync(0xffffffffu, rm0, 1));
        rm0 = fmaxf(rm0, __shfl_xor_sync(0xffffffffu, rm0, 2));
        rm1 = fmaxf(rm1, __shfl_xor_sync(0xffffffffu, rm1, 1));
        rm1 = fmaxf(rm1, __shfl_xor_sync(0xffffffffu, rm1, 2));
        float nm0 = fmaxf(m0r, rm0), nm1 = fmaxf(m1r, rm1);

        float rs0 = 0.f, rs1 = 0.f;
        #pragma unroll
        for (int nt = 0; nt < 4; ++nt) {
            p[nt][0] = __expf(p[nt][0] - nm0);
            p[nt][1] = __expf(p[nt][1] - nm0);
            p[nt][2] = __expf(p[nt][2] - nm1);
            p[nt][3] = __expf(p[nt][3] - nm1);
            rs0 += p[nt][0] + p[nt][1];
            rs1 += p[nt][2] + p[nt][3];
        }
        rs0 += __shfl_xor_sync(0xffffffffu, rs0, 1);
        rs0 += __shfl_xor_sync(0xffffffffu, rs0, 2);
        rs1 += __shfl_xor_sync(0xffffffffu, rs1, 1);
        rs1 += __shfl_xor_sync(0xffffffffu, rs1, 2);

        uint32_t need = __ballot_sync(0xffffffffu, (nm0 > m0r) || (nm1 > m1r));
        if (need) {
            float al0 = __expf(m0r - nm0), al1 = __expf(m1r - nm1);
            #pragma unroll
            for (int i = 0; i < 16; i++) {
                o[i][0] *= al0; o[i][1] *= al0;
                o[i][2] *= al1; o[i][3] *= al1;
            }
            l0r = l0r * al0 + rs0;
            l1r = l1r * al1 + rs1;
        } else {
            l0r += rs0;
            l1r += rs1;
        }
        m0r = nm0; m1r = nm1;

        uint32_t pF[2][4];
        #pragma unroll
        for (int ks2 = 0; ks2 < 2; ++ks2) {
            #pragma unroll
            for (int half = 0; half < 2; ++half) {
                int nt = 2 * ks2 + half;
                #pragma unroll
                for (int rr = 0; rr < 2; ++rr) {
                    __half2 hp = __floats2half2_rn(p[nt][2*rr], p[nt][2*rr+1]);
                    pF[ks2][half*2 + rr] = *(uint32_t*)&hp;
                }
            }
        }

        #pragma unroll
        for (int ks2 = 0; ks2 < 2; ++ks2) {
            #pragma unroll
            for (int vb = 0; vb < 8; ++vb) {
                uint32_t h0, h1, h2, h3;
                LDSM4T(h0, h1, h2, h3,
                       st + VOFF + vTrow + ks2 * 16 * QPITCH + vb * 32);
                uint32_t b0[2] = {h0, h1}, b1[2] = {h2, h3};
                MMA16816H(o[2*vb],   pF[ks2], b0);
                MMA16816H(o[2*vb+1], pF[ks2], b1);
            }
        }
    }

    float i0 = 1.0f / l0r, i1 = 1.0f / l1r;
    int r0 = qt * 128 + wid * 16 + (lane >> 2);
    size_t base0 = ((size_t)b * S_ + r0) * H_ + h * HD_ + (lane & 3) * 2;
    size_t base1 = base0 + (size_t)8 * H_;
    #pragma unroll
    for (int nt = 0; nt < 16; ++nt) {
        store_split_h(Oh, Ol, base0 + nt * 8, make_float2(o[nt][0] * i0, o[nt][1] * i0));
        store_split_h(Oh, Ol, base1 + nt * 8, make_float2(o[nt][2] * i1, o[nt][3] * i1));
    }
}

// ---------------- launch ----------------
extern "C" void kernel_launch(void* const* d_in, const int* in_sizes, int n_in,
                              void* d_out, int out_size) {
    (void)in_sizes; (void)n_in; (void)out_size;
    const float* x   = (const float*)d_in[0];
    const float* msk = (const float*)d_in[1];
    const float* kc  = (const float*)d_in[2];
    const float* vc  = (const float*)d_in[3];
    const float* Wq  = (const float*)d_in[4];
    const float* bq  = (const float*)d_in[5];
    const float* Wk  = (const float*)d_in[6];
    const float* bk  = (const float*)d_in[7];
    const float* Wv  = (const float*)d_in[8];
    const float* bv  = (const float*)d_in[9];
    const float* Wo  = (const float*)d_in[10];
    const float* bo  = (const float*)d_in[11];

    float* out = (float*)d_out;
    float* ko  = out + (size_t)B_ * S_ * H_;
    float* vo  = ko  + (size_t)B_ * NH_ * KV_ * HD_;

    __half *xh, *xl, *wq, *wk, *wv, *wo, *qf, *kf, *vf, *ah, *al;
    cudaGetSymbolAddress((void**)&xh, sXh); cudaGetSymbolAddress((void**)&xl, sXl);
    cudaGetSymbolAddress((void**)&wq, sWq); cudaGetSymbolAddress((void**)&wk, sWk);
    cudaGetSymbolAddress((void**)&wv, sWv); cudaGetSymbolAddress((void**)&wo, sWo);
    cudaGetSymbolAddress((void**)&qf, sQf); cudaGetSymbolAddress((void**)&kf, sKf);
    cudaGetSymbolAddress((void**)&vf, sVf);
    cudaGetSymbolAddress((void**)&ah, sAh); cudaGetSymbolAddress((void**)&al, sAl);

    cudaFuncSetAttribute(gemm_qkv,
                         cudaFuncAttributeMaxDynamicSharedMemorySize, GT_SMEM);
    cudaFuncSetAttribute(gemm_out,
                         cudaFuncAttributeMaxDynamicSharedMemorySize, GT_SMEM);
    cudaFuncSetAttribute(attn_mma,
                         cudaFuncAttributeMaxDynamicSharedMemorySize, ATT_SMEM);

    // 1. splice caches into output k/v (+ fp16 copies for attention)
    copy_cache_kernel<<<8192, 256>>>((const float4*)kc, (const float4*)vc,
                                     (float4*)ko, (float4*)vo,
                                     (uint2*)kf, (uint2*)vf);

    // 2. activations: fp16 hi/lo split; weights: plain fp16
    split_h_kernel<<<8192, 256>>>((const float4*)x, (uint2*)xh, (uint2*)xl);
    convert4_kernel<<<dim3(4096, 4), 256>>>(
        (const float4*)Wq, (const float4*)Wk, (const float4*)Wv, (const float4*)Wo,
        (uint2*)wq, (uint2*)wk, (uint2*)wv, (uint2*)wo);

    // 3. fused QKV projections (fp16 2-term); q pre-scaled by 1/sqrt(HD)
    gemm_qkv<<<dim3(H_/128, M_/128, 3), 512, GT_SMEM>>>(
        xh, xl, wq, wk, wv, bq, bk, bv, ko, vo, qf, kf, vf);

    // 4. attention (fp16 operands, fp32 softmax); emits fp16 output splits
    attn_mma<<<dim3(S_/128, NH_, B_), 256, ATT_SMEM>>>(qf, kf, vf, msk, ah, al);

    // 5. output projection (fp16 2-term)
    gemm_out<<<dim3(H_/128, M_/128), 512, GT_SMEM>>>(ah, al, wo, bo, out);
}